// round 9
// baseline (speedup 1.0000x reference)
#include <cuda_runtime.h>
#include <cuda_bf16.h>
#include <cstdint>

// StackLSTM T=256, B=64, H=1024, L=2 — Round 9.
// mma.sync bf16 3-term split (a_hi@Whi + a_hi@Wlo + a_lo@Whi), fp32 accum.
// R9 = R8 (register fragment double-buffer) with the RACE FIXED:
// per chunk: own cp.async wait -> group barrier (all warps' stores visible)
// -> LDSM next chunk -> issue load i+4 -> HMMA current chunk.

#define Tt 256
#define Bb 64
#define Hh 1024
#define BH (Bb * Hh)                 // 65536
#define M4H 4096
#define KK 2048
#define WPL (2ULL * M4H * KK)        // bf16 elems per layer (hi+lo)
#define STAGE 24576                  // A 8KB (hi+lo) + B 16KB (hi+lo)
#define NSTAGE 4
#define GSZ (NSTAGE * STAGE)         // 98304 per group
#define SMEM_TOTAL (2 * GSZ)         // 196608

// ---------------- persistent device state ----------------
__device__ __nv_bfloat16 g_xhi[Tt * BH];
__device__ __nv_bfloat16 g_xlo[Tt * BH];
__device__ __nv_bfloat16 g_W[2 * WPL];       // [layer][hl][4096 perm rows][2048]
__device__ float         g_bsum[2 * M4H];
__device__ __nv_bfloat16 g_Hhi[2 * 2 * BH];  // [layer][parity][BH]
__device__ __nv_bfloat16 g_Hlo[2 * 2 * BH];
__device__ float         g_C[2 * BH];
__device__ float         g_Hf[2 * BH];

// ---------------- helpers ----------------
__device__ __forceinline__ uint32_t smem_u32(const void* p) {
    uint32_t a;
    asm("{ .reg .u64 t; cvta.to.shared.u64 t, %1; cvt.u32.u64 %0, t; }"
        : "=r"(a) : "l"(p));
    return a;
}
__device__ __forceinline__ void cp16(uint32_t d, const void* g) {
    asm volatile("cp.async.cg.shared.global [%0], [%1], 16;"
                 :: "r"(d), "l"(g) : "memory");
}
#define CP_COMMIT() asm volatile("cp.async.commit_group;" ::: "memory")
#define CP_WAIT3()  asm volatile("cp.async.wait_group 3;" ::: "memory")
#define CP_WAIT2()  asm volatile("cp.async.wait_group 2;" ::: "memory")
#define CP_WAIT1()  asm volatile("cp.async.wait_group 1;" ::: "memory")
#define CP_WAIT0()  asm volatile("cp.async.wait_group 0;" ::: "memory")

#define LDSM4(r, addr) \
    asm volatile("ldmatrix.sync.aligned.m8n8.x4.shared.b16 {%0,%1,%2,%3}, [%4];" \
        : "=r"((r)[0]), "=r"((r)[1]), "=r"((r)[2]), "=r"((r)[3]) : "r"(addr))

#define HMMA(d, a0, a1, a2, a3, b0, b1) \
    asm volatile("mma.sync.aligned.m16n8k16.row.col.f32.bf16.bf16.f32 " \
        "{%0,%1,%2,%3},{%4,%5,%6,%7},{%8,%9},{%0,%1,%2,%3};" \
        : "+f"((d)[0]), "+f"((d)[1]), "+f"((d)[2]), "+f"((d)[3]) \
        : "r"(a0), "r"(a1), "r"(a2), "r"(a3), "r"(b0), "r"(b1))

__device__ __forceinline__ void gbar(int grp) {
    if (grp == 0) asm volatile("bar.sync 1, 256;" ::: "memory");
    else          asm volatile("bar.sync 2, 256;" ::: "memory");
}

__device__ __forceinline__ float sigm(float x) { return 1.0f / (1.0f + __expf(-x)); }
__device__ __forceinline__ float tanh_(float x) {
    float ax = fabsf(x);
    float e  = __expf(-2.0f * ax);
    return copysignf((1.0f - e) / (1.0f + e), x);
}

struct Frags {
    uint32_t ah0[4], ah1[4], al0[4], al1[4];
    uint32_t bh0[4], bh1[4], bl0[4], bl1[4];
};

// ---------------- prep kernels ----------------
__global__ void split_x_kernel(const float* __restrict__ x, int n) {
    for (int i = blockIdx.x * blockDim.x + threadIdx.x; i < n;
         i += gridDim.x * blockDim.x) {
        float v = x[i];
        __nv_bfloat16 hi = __float2bfloat16(v);
        g_xhi[i] = hi;
        g_xlo[i] = __float2bfloat16(v - __bfloat162float(hi));
    }
}

__global__ void init_state_kernel(const float* __restrict__ h0,
                                  const float* __restrict__ c0,
                                  const float* __restrict__ bih,
                                  const float* __restrict__ bhh) {
    int t0 = blockIdx.x * blockDim.x + threadIdx.x;
    for (int idx = t0; idx < 2 * BH; idx += gridDim.x * blockDim.x) {
        int l = idx / BH, r = idx % BH;
        float hv = h0[idx];
        __nv_bfloat16 hi = __float2bfloat16(hv);
        g_Hhi[(l * 2 + 0) * BH + r] = hi;
        g_Hlo[(l * 2 + 0) * BH + r] = __float2bfloat16(hv - __bfloat162float(hi));
        g_C[idx] = c0[idx];
    }
    for (int idx = t0; idx < 2 * M4H; idx += gridDim.x * blockDim.x)
        g_bsum[idx] = bih[idx] + bhh[idx];
}

// g_W[l][hl][p][k]: permuted row p: blk=p>>5, lcl=p&31, gate=lcl>>3, jl=lcl&7,
// j=blk*8+jl, source row = gate*1024+j. k<1024 -> Wih, else Whh.
__global__ void prep_w_kernel(const float* __restrict__ Wih,
                              const float* __restrict__ Whh) {
    const long long per = (long long)M4H * KK;
    const long long n   = 2 * 2 * per;
    for (long long idx = blockIdx.x * (long long)blockDim.x + threadIdx.x; idx < n;
         idx += (long long)gridDim.x * blockDim.x) {
        int  l  = (int)(idx / (2 * per));
        long long r1 = idx % (2 * per);
        int  hl = (int)(r1 / per);
        long long r2 = r1 % per;
        int  p  = (int)(r2 / KK), k = (int)(r2 % KK);
        int  blk = p >> 5, lcl = p & 31;
        int  gate = lcl >> 3, jl = lcl & 7;
        int  j = blk * 8 + jl;
        int  srow = gate * 1024 + j;
        float w = (k < 1024)
                ? Wih[(size_t)l * M4H * Hh + (size_t)srow * Hh + k]
                : Whh[(size_t)l * M4H * Hh + (size_t)srow * Hh + (k - 1024)];
        __nv_bfloat16 hi = __float2bfloat16(w);
        g_W[idx] = hl ? __float2bfloat16(w - __bfloat162float(hi)) : hi;
    }
}

// ---------------- main layer-step kernel ----------------
// grid = 128 CTAs (M=32 gate-rows), block = 512 (2 K-split groups x 8 warps).
// Warp: sub = k16 slot (0..3) of each K64 chunk, half = N32 half; M32xN32.
__global__ void __launch_bounds__(512, 1) lstm_step_mma(
    const __nv_bfloat16* __restrict__ W,     // this layer: [2][4096][2048]
    const float*         __restrict__ bsum,  // [4096]
    const __nv_bfloat16* __restrict__ xhi,   // [64][1024]
    const __nv_bfloat16* __restrict__ xlo,
    const __nv_bfloat16* __restrict__ hhi,
    const __nv_bfloat16* __restrict__ hlo,
    __nv_bfloat16* __restrict__ ohi,
    __nv_bfloat16* __restrict__ olo,
    float* __restrict__ C,
    float* __restrict__ Hf)
{
    extern __shared__ char smem[];
    const int tid  = threadIdx.x;
    const int grp  = tid >> 8;           // K-split group: 0 -> x half, 1 -> h half
    const int gtid = tid & 255;
    const int gwid = gtid >> 5, lane = tid & 31;
    const int blk  = blockIdx.x;
    const int sub  = gwid >> 1;          // k16 index within K64 chunk (0..3)
    const int half = gwid & 1;           // N32 half (0..1)
    const uint32_t sb = smem_u32(smem) + grp * GSZ;

    // fragment addressing (swizzled smem, 128B rows)
    const int rA  = lane & 15;
    const int rB  = (lane & 7) + ((lane >> 4) << 3);
    const uint32_t qa = 2 * sub + (lane >> 4);
    const uint32_t qb = 2 * sub + ((lane >> 3) & 1);
    const uint32_t aOff = rA * 128 + (((qa ^ (rA & 7))) << 4);
    const uint32_t bOff = (half * 32 + rB) * 128 + (((qb ^ (rB & 7))) << 4);

    const __nv_bfloat16* bh_src = grp ? hhi : xhi;
    const __nv_bfloat16* bl_src = grp ? hlo : xlo;
    const __nv_bfloat16* Wbase  = W + (size_t)(blk * 32) * KK + grp * 1024;

    float acc[8][4];
#pragma unroll
    for (int i = 0; i < 8; i++)
#pragma unroll
        for (int r = 0; r < 4; r++) acc[i][r] = 0.f;

    auto load_chunk = [&](int lc) {
        const int st = lc & 3;
        const uint32_t stA = sb + st * STAGE;
        const uint32_t stB = stA + 8192;
        const int koff = lc * 64;
#pragma unroll
        for (int i = 0; i < 2; i++) {
            int u = gtid + i * 256;
            int hl = u >> 8, rem = u & 255, row = rem >> 3, q = rem & 7;
            const __nv_bfloat16* s = Wbase + (size_t)hl * (M4H * KK)
                                   + (size_t)row * KK + koff + q * 8;
            cp16(stA + hl * 4096 + row * 128 + ((q ^ (row & 7)) << 4), s);
        }
#pragma unroll
        for (int i = 0; i < 4; i++) {
            int u = gtid + i * 256;
            int hl = u >> 9, rem = u & 511, row = rem >> 3, q = rem & 7;
            const __nv_bfloat16* s =
                (hl ? bl_src : bh_src) + (size_t)row * 1024 + koff + q * 8;
            cp16(stB + hl * 8192 + row * 128 + ((q ^ (row & 7)) << 4), s);
        }
        CP_COMMIT();
    };

    auto ldsm_all = [&](int lc, Frags& f) {
        const uint32_t stA = sb + (lc & 3) * STAGE;
        const uint32_t stB = stA + 8192;
        LDSM4(f.ah0, stA + aOff);
        LDSM4(f.ah1, stA + aOff + 2048);
        LDSM4(f.al0, stA + aOff + 4096);
        LDSM4(f.al1, stA + aOff + 6144);
        LDSM4(f.bh0, stB + bOff);
        LDSM4(f.bh1, stB + bOff + 2048);
        LDSM4(f.bl0, stB + bOff + 8192);
        LDSM4(f.bl1, stB + bOff + 10240);
    };

    auto hmma_all = [&](const Frags& f) {
#pragma unroll
        for (int t = 0; t < 3; t++) {
            const uint32_t* a0 = (t == 2) ? f.al0 : f.ah0;
            const uint32_t* a1 = (t == 2) ? f.al1 : f.ah1;
            const uint32_t* b0 = (t == 1) ? f.bl0 : f.bh0;
            const uint32_t* b1 = (t == 1) ? f.bl1 : f.bh1;
            HMMA(acc[0], a0[0], a0[1], a0[2], a0[3], b0[0], b0[1]);
            HMMA(acc[1], a0[0], a0[1], a0[2], a0[3], b0[2], b0[3]);
            HMMA(acc[2], a0[0], a0[1], a0[2], a0[3], b1[0], b1[1]);
            HMMA(acc[3], a0[0], a0[1], a0[2], a0[3], b1[2], b1[3]);
            HMMA(acc[4], a1[0], a1[1], a1[2], a1[3], b0[0], b0[1]);
            HMMA(acc[5], a1[0], a1[1], a1[2], a1[3], b0[2], b0[3]);
            HMMA(acc[6], a1[0], a1[1], a1[2], a1[3], b1[0], b1[1]);
            HMMA(acc[7], a1[0], a1[1], a1[2], a1[3], b1[2], b1[3]);
        }
    };

    // body for chunk i (RACE-FIXED ordering):
    //  1. wait own cp.async so chunk i+1 (this warp's parts) is complete
    //  2. group barrier -> ALL warps' chunk i+1 stores visible; also proves
    //     all warps LDSM'd chunk i (done in body(i-1)) -> stage i&3 reusable
    //  3. LDSM chunk i+1 fragments (overlaps with 4's loads and 5's HMMAs)
    //  4. issue load of chunk i+4 into stage (i+4)&3 = i&3
    //  5. HMMA chunk i from current fragments
    auto body = [&](int i, Frags& cur, Frags& nxt) {
        if (i <= 12)      CP_WAIT2();
        else if (i == 13) CP_WAIT1();
        else if (i == 14) CP_WAIT0();
        gbar(grp);
        if (i < 15) ldsm_all(i + 1, nxt);
        if (i + 4 < 16) load_chunk(i + 4);
        hmma_all(cur);
    };

    // prologue: fill 4 stages, fetch chunk 0 frags
    load_chunk(0); load_chunk(1); load_chunk(2); load_chunk(3);
    CP_WAIT3();                          // own chunk-0 parts complete
    gbar(grp);                           // chunk 0 fully visible group-wide
    Frags f0, f1;
    ldsm_all(0, f0);

    for (int i = 0; i < 16; i += 2) {
        body(i,     f0, f1);
        body(i + 1, f1, f0);
    }

    // ---------------- epilogue: 8 partials -> fused LSTM cell -------------
    __syncthreads();                      // both groups done; overlay stages
    float* gb = (float*)smem;             // [8 partial][32 m][66]
    {
        float* myb = gb + (grp * 4 + sub) * (32 * 66);
        const int mrow = lane >> 2;
        const int ncol = 2 * (lane & 3);
#pragma unroll
        for (int i = 0; i < 8; i++) {
            const int mt = i >> 2, nt = (i >> 1) & 1, u = i & 1;
            const int m = mt * 16 + mrow;
            const int n = half * 32 + nt * 16 + u * 8 + ncol;
            *(float2*)&myb[m * 66 + n]       = make_float2(acc[i][0], acc[i][1]);
            *(float2*)&myb[(m + 8) * 66 + n] = make_float2(acc[i][2], acc[i][3]);
        }
    }
    __syncthreads();

    const int jl = tid & 7;
    const int b  = tid >> 3;              // 0..63
    const int j  = blk * 8 + jl;
    float gsum[4];
#pragma unroll
    for (int g = 0; g < 4; g++) {
        float s = 0.f;
#pragma unroll
        for (int p = 0; p < 8; p++)
            s += gb[(p * 32 + g * 8 + jl) * 66 + b];
        gsum[g] = s;
    }
    float gi = gsum[0] + bsum[j];
    float gf = gsum[1] + bsum[1024 + j];
    float gg = gsum[2] + bsum[2048 + j];
    float go = gsum[3] + bsum[3072 + j];
    float cn = sigm(gf) * C[b * Hh + j] + sigm(gi) * tanh_(gg);
    C[b * Hh + j] = cn;
    float hn = sigm(go) * tanh_(cn);
    Hf[b * Hh + j] = hn;
    __nv_bfloat16 hi = __float2bfloat16(hn);
    ohi[b * Hh + j] = hi;
    olo[b * Hh + j] = __float2bfloat16(hn - __bfloat162float(hi));
}

// ---------------- host launcher ----------------
extern "C" void kernel_launch(void* const* d_in, const int* in_sizes, int n_in,
                              void* d_out, int out_size) {
    const float* x_seq = (const float*)d_in[0];
    const float* h0    = (const float*)d_in[1];
    const float* c0    = (const float*)d_in[2];
    const float* Wih   = (const float*)d_in[3];
    const float* Whh   = (const float*)d_in[4];
    const float* bih   = (const float*)d_in[5];
    const float* bhh   = (const float*)d_in[6];

    cudaFuncSetAttribute(lstm_step_mma,
                         cudaFuncAttributeMaxDynamicSharedMemorySize, SMEM_TOTAL);

    void *p_xhi, *p_xlo, *p_w, *p_bs, *p_hhi, *p_hlo, *p_c, *p_hf;
    cudaGetSymbolAddress(&p_xhi, g_xhi);
    cudaGetSymbolAddress(&p_xlo, g_xlo);
    cudaGetSymbolAddress(&p_w,   g_W);
    cudaGetSymbolAddress(&p_bs,  g_bsum);
    cudaGetSymbolAddress(&p_hhi, g_Hhi);
    cudaGetSymbolAddress(&p_hlo, g_Hlo);
    cudaGetSymbolAddress(&p_c,   g_C);
    cudaGetSymbolAddress(&p_hf,  g_Hf);

    __nv_bfloat16* xhi = (__nv_bfloat16*)p_xhi;
    __nv_bfloat16* xlo = (__nv_bfloat16*)p_xlo;
    __nv_bfloat16* Wg  = (__nv_bfloat16*)p_w;
    float*         bs  = (float*)p_bs;
    __nv_bfloat16* Hhi = (__nv_bfloat16*)p_hhi;
    __nv_bfloat16* Hlo = (__nv_bfloat16*)p_hlo;
    float*         Cst = (float*)p_c;
    float*         Hf  = (float*)p_hf;

    split_x_kernel<<<8192, 256>>>(x_seq, Tt * BH);
    init_state_kernel<<<512, 256>>>(h0, c0, bih, bhh);
    prep_w_kernel<<<8192, 256>>>(Wih, Whh);

    for (int t = 0; t < Tt; t++) {
        const int p = t & 1;
        // layer 0
        lstm_step_mma<<<128, 512, SMEM_TOTAL>>>(
            Wg, bs,
            xhi + (size_t)t * BH, xlo + (size_t)t * BH,
            Hhi + (size_t)p * BH, Hlo + (size_t)p * BH,
            Hhi + (size_t)(p ^ 1) * BH, Hlo + (size_t)(p ^ 1) * BH,
            Cst, Hf);
        // layer 1 (input = layer 0's fresh hidden, already split)
        lstm_step_mma<<<128, 512, SMEM_TOTAL>>>(
            Wg + WPL, bs + M4H,
            Hhi + (size_t)(p ^ 1) * BH, Hlo + (size_t)(p ^ 1) * BH,
            Hhi + (size_t)(2 + p) * BH, Hlo + (size_t)(2 + p) * BH,
            Hhi + (size_t)(2 + (p ^ 1)) * BH, Hlo + (size_t)(2 + (p ^ 1)) * BH,
            Cst + BH, Hf + BH);
    }
    cudaMemcpyAsync(d_out, Hf + BH, (size_t)BH * sizeof(float),
                    cudaMemcpyDeviceToDevice);
}

// round 10
// speedup vs baseline: 1.2766x; 1.2766x over previous
#include <cuda_runtime.h>
#include <cuda_bf16.h>
#include <cstdint>

// StackLSTM T=256, B=64, H=1024, L=2 — Round 10.
// mma.sync bf16 3-term split (a_hi@Whi + a_hi@Wlo + a_lo@Whi), fp32 accum.
// R10: WAVE FUSION. layer0[w] and layer1[w-1] are mutually independent ->
// one kernel launch per wave, 128 CTAs: blocks 0..63 = layer0[w] (M64 tile),
// blocks 64..127 = layer1[w-1]. 512 launches -> 257; per-CTA M-tile doubles
// (better A-fragment reuse: 48 HMMA per chunk vs 24, same LDSM A bytes).

#define Tt 256
#define Bb 64
#define Hh 1024
#define BH (Bb * Hh)                 // 65536
#define M4H 4096
#define KK 2048
#define WPL (2ULL * M4H * KK)        // bf16 elems per layer (hi+lo)
#define STAGE 32768                  // A 16KB (hi+lo) + B 16KB (hi+lo)
#define NSTAGE 3
#define GSZ (NSTAGE * STAGE)         // 98304 per group
#define SMEM_TOTAL (2 * GSZ)         // 196608

// ---------------- persistent device state ----------------
__device__ __nv_bfloat16 g_xhi[Tt * BH];
__device__ __nv_bfloat16 g_xlo[Tt * BH];
__device__ __nv_bfloat16 g_W[2 * WPL];       // [layer][hl][4096 perm rows][2048]
__device__ float         g_bsum[2 * M4H];
__device__ __nv_bfloat16 g_Hhi[2 * 2 * BH];  // [layer][parity][BH]
__device__ __nv_bfloat16 g_Hlo[2 * 2 * BH];
__device__ float         g_C[2 * BH];
__device__ float         g_Hf[BH];           // final top-layer hidden (fp32)

// ---------------- helpers ----------------
__device__ __forceinline__ uint32_t smem_u32(const void* p) {
    uint32_t a;
    asm("{ .reg .u64 t; cvta.to.shared.u64 t, %1; cvt.u32.u64 %0, t; }"
        : "=r"(a) : "l"(p));
    return a;
}
__device__ __forceinline__ void cp16(uint32_t d, const void* g) {
    asm volatile("cp.async.cg.shared.global [%0], [%1], 16;"
                 :: "r"(d), "l"(g) : "memory");
}
#define CP_COMMIT() asm volatile("cp.async.commit_group;" ::: "memory")
#define CP_WAIT1()  asm volatile("cp.async.wait_group 1;" ::: "memory")
#define CP_WAIT0()  asm volatile("cp.async.wait_group 0;" ::: "memory")

#define LDSM4(r, addr) \
    asm volatile("ldmatrix.sync.aligned.m8n8.x4.shared.b16 {%0,%1,%2,%3}, [%4];" \
        : "=r"((r)[0]), "=r"((r)[1]), "=r"((r)[2]), "=r"((r)[3]) : "r"(addr))

#define HMMA(d, a0, a1, a2, a3, b0, b1) \
    asm volatile("mma.sync.aligned.m16n8k16.row.col.f32.bf16.bf16.f32 " \
        "{%0,%1,%2,%3},{%4,%5,%6,%7},{%8,%9},{%0,%1,%2,%3};" \
        : "+f"((d)[0]), "+f"((d)[1]), "+f"((d)[2]), "+f"((d)[3]) \
        : "r"(a0), "r"(a1), "r"(a2), "r"(a3), "r"(b0), "r"(b1))

__device__ __forceinline__ void gbar(int grp) {
    if (grp == 0) asm volatile("bar.sync 1, 256;" ::: "memory");
    else          asm volatile("bar.sync 2, 256;" ::: "memory");
}

__device__ __forceinline__ float sigm(float x) { return 1.0f / (1.0f + __expf(-x)); }
__device__ __forceinline__ float tanh_(float x) {
    float ax = fabsf(x);
    float e  = __expf(-2.0f * ax);
    return copysignf((1.0f - e) / (1.0f + e), x);
}

// ---------------- prep kernels ----------------
__global__ void split_x_kernel(const float* __restrict__ x, int n) {
    for (int i = blockIdx.x * blockDim.x + threadIdx.x; i < n;
         i += gridDim.x * blockDim.x) {
        float v = x[i];
        __nv_bfloat16 hi = __float2bfloat16(v);
        g_xhi[i] = hi;
        g_xlo[i] = __float2bfloat16(v - __bfloat162float(hi));
    }
}

__global__ void init_state_kernel(const float* __restrict__ h0,
                                  const float* __restrict__ c0,
                                  const float* __restrict__ bih,
                                  const float* __restrict__ bhh) {
    int t0 = blockIdx.x * blockDim.x + threadIdx.x;
    for (int idx = t0; idx < 2 * BH; idx += gridDim.x * blockDim.x) {
        int l = idx / BH, r = idx % BH;
        float hv = h0[idx];
        __nv_bfloat16 hi = __float2bfloat16(hv);
        g_Hhi[(l * 2 + 0) * BH + r] = hi;
        g_Hlo[(l * 2 + 0) * BH + r] = __float2bfloat16(hv - __bfloat162float(hi));
        g_C[idx] = c0[idx];
    }
    for (int idx = t0; idx < 2 * M4H; idx += gridDim.x * blockDim.x)
        g_bsum[idx] = bih[idx] + bhh[idx];
}

// g_W[l][hl][p][k]: permuted row p: blk=p>>5, lcl=p&31, gate=lcl>>3, jl=lcl&7,
// j=blk*8+jl, source row = gate*1024+j. k<1024 -> Wih, else Whh.
__global__ void prep_w_kernel(const float* __restrict__ Wih,
                              const float* __restrict__ Whh) {
    const long long per = (long long)M4H * KK;
    const long long n   = 2 * 2 * per;
    for (long long idx = blockIdx.x * (long long)blockDim.x + threadIdx.x; idx < n;
         idx += (long long)gridDim.x * blockDim.x) {
        int  l  = (int)(idx / (2 * per));
        long long r1 = idx % (2 * per);
        int  hl = (int)(r1 / per);
        long long r2 = r1 % per;
        int  p  = (int)(r2 / KK), k = (int)(r2 % KK);
        int  blk = p >> 5, lcl = p & 31;
        int  gate = lcl >> 3, jl = lcl & 7;
        int  j = blk * 8 + jl;
        int  srow = gate * 1024 + j;
        float w = (k < 1024)
                ? Wih[(size_t)l * M4H * Hh + (size_t)srow * Hh + k]
                : Whh[(size_t)l * M4H * Hh + (size_t)srow * Hh + (k - 1024)];
        __nv_bfloat16 hi = __float2bfloat16(w);
        g_W[idx] = hl ? __float2bfloat16(w - __bfloat162float(hi)) : hi;
    }
}

// ---------------- wave kernel: layer0[w] || layer1[w-1] ----------------
// grid = 128: blocks 0..63 role 0 (layer0, M64 tile mblk), 64..127 role 1.
// block = 512 = 2 K-split groups x 8 warps; warp: sub = k16 slot, half = N32.
// Warp tile M64 x N32 (4 m16 tiles), 48 HMMA per K64 chunk.
__global__ void __launch_bounds__(512, 1) lstm_wave(
    const __nv_bfloat16* __restrict__ W,
    const float*         __restrict__ bsum,
    const __nv_bfloat16* __restrict__ xhi,
    const __nv_bfloat16* __restrict__ xlo,
    __nv_bfloat16* __restrict__ Hhi,
    __nv_bfloat16* __restrict__ Hlo,
    float* __restrict__ C,
    float* __restrict__ Hf,
    int w)
{
    const int role = blockIdx.x >> 6;
    const int mblk = blockIdx.x & 63;
    if (role == 0 && w >= Tt) return;
    if (role == 1 && w == 0)  return;

    const int tt = role ? (w - 1) : w;
    const int p  = tt & 1;

    // per-role sources/sinks
    const __nv_bfloat16 *xs_hi, *xs_lo, *hs_hi, *hs_lo;
    __nv_bfloat16 *o_hi, *o_lo;
    const __nv_bfloat16* Wl;
    const float* bs;
    float* Cl;
    if (role == 0) {
        xs_hi = xhi + (size_t)tt * BH;  xs_lo = xlo + (size_t)tt * BH;
        hs_hi = Hhi + (size_t)p * BH;   hs_lo = Hlo + (size_t)p * BH;
        o_hi  = Hhi + (size_t)(p ^ 1) * BH;
        o_lo  = Hlo + (size_t)(p ^ 1) * BH;
        Wl = W; bs = bsum; Cl = C;
    } else {
        // x = layer0 output at time tt = H0[(tt&1)^1]
        xs_hi = Hhi + (size_t)(p ^ 1) * BH;  xs_lo = Hlo + (size_t)(p ^ 1) * BH;
        hs_hi = Hhi + (size_t)(2 + p) * BH;  hs_lo = Hlo + (size_t)(2 + p) * BH;
        o_hi  = Hhi + (size_t)(2 + (p ^ 1)) * BH;
        o_lo  = Hlo + (size_t)(2 + (p ^ 1)) * BH;
        Wl = W + WPL; bs = bsum + M4H; Cl = C + BH;
    }

    extern __shared__ char smem[];
    const int tid  = threadIdx.x;
    const int grp  = tid >> 8;           // K-split group: 0 -> x half, 1 -> h half
    const int gtid = tid & 255;
    const int gwid = gtid >> 5, lane = tid & 31;
    const int sub  = gwid >> 1;          // k16 index within K64 chunk
    const int half = gwid & 1;           // N32 half
    const uint32_t sb = smem_u32(smem) + grp * GSZ;

    // fragment addressing (swizzled smem, 128B rows)
    const int rA  = lane & 15;
    const int rB  = (lane & 7) + ((lane >> 4) << 3);
    const uint32_t qa = 2 * sub + (lane >> 4);
    const uint32_t qb = 2 * sub + ((lane >> 3) & 1);
    const uint32_t aOff = rA * 128 + (((qa ^ (rA & 7))) << 4);
    const uint32_t bOff = (half * 32 + rB) * 128 + (((qb ^ (rB & 7))) << 4);

    const __nv_bfloat16* bh_src = grp ? hs_hi : xs_hi;
    const __nv_bfloat16* bl_src = grp ? hs_lo : xs_lo;
    const __nv_bfloat16* Wbase  = Wl + (size_t)(mblk * 64) * KK + grp * 1024;

    // M64xN32 accumulators: acc[mt*4 + n8] (mt 0..3, n8 0..3)
    float acc[16][4];
#pragma unroll
    for (int i = 0; i < 16; i++)
#pragma unroll
        for (int r = 0; r < 4; r++) acc[i][r] = 0.f;

    auto load_chunk = [&](int lc) {
        const int st = lc % 3;
        const uint32_t stA = sb + st * STAGE;
        const uint32_t stB = stA + 16384;
        const int koff = lc * 64;
        // A: [2 hl][64 rows][8 q] = 1024 16B units; 4/thread
#pragma unroll
        for (int i = 0; i < 4; i++) {
            int u = gtid + i * 256;
            int hl = u >> 9, rem = u & 511, row = rem >> 3, q = rem & 7;
            const __nv_bfloat16* s = Wbase + (size_t)hl * (M4H * KK)
                                   + (size_t)row * KK + koff + q * 8;
            cp16(stA + hl * 8192 + row * 128 + ((q ^ (row & 7)) << 4), s);
        }
        // B: [2 hl][64 rows][8 q] = 1024 units; 4/thread
#pragma unroll
        for (int i = 0; i < 4; i++) {
            int u = gtid + i * 256;
            int hl = u >> 9, rem = u & 511, row = rem >> 3, q = rem & 7;
            const __nv_bfloat16* s =
                (hl ? bl_src : bh_src) + (size_t)row * 1024 + koff + q * 8;
            cp16(stB + hl * 8192 + row * 128 + ((q ^ (row & 7)) << 4), s);
        }
        CP_COMMIT();
    };

    load_chunk(0);
    load_chunk(1);

    for (int lc = 0; lc < 16; ++lc) {
        if (lc <= 14) CP_WAIT1();
        else          CP_WAIT0();
        gbar(grp);
        if (lc + 2 < 16) load_chunk(lc + 2);

        const uint32_t stA = sb + (lc % 3) * STAGE;
        const uint32_t stB = stA + 16384;

        uint32_t a0[4], a1[4], a2[4], a3[4];
        uint32_t b0h[4], b1h[4], b0l[4], b1l[4];
        LDSM4(a0, stA + aOff);
        LDSM4(a1, stA + aOff + 2048);
        LDSM4(a2, stA + aOff + 4096);
        LDSM4(a3, stA + aOff + 6144);
        LDSM4(b0h, stB + bOff);
        LDSM4(b1h, stB + bOff + 2048);
        LDSM4(b0l, stB + bOff + 8192);
        LDSM4(b1l, stB + bOff + 10240);

        // term0: a_hi x b_hi ; term1: a_hi x b_lo
        HMMA(acc[0],  a0[0],a0[1],a0[2],a0[3], b0h[0],b0h[1]);
        HMMA(acc[1],  a0[0],a0[1],a0[2],a0[3], b0h[2],b0h[3]);
        HMMA(acc[2],  a0[0],a0[1],a0[2],a0[3], b1h[0],b1h[1]);
        HMMA(acc[3],  a0[0],a0[1],a0[2],a0[3], b1h[2],b1h[3]);
        HMMA(acc[4],  a1[0],a1[1],a1[2],a1[3], b0h[0],b0h[1]);
        HMMA(acc[5],  a1[0],a1[1],a1[2],a1[3], b0h[2],b0h[3]);
        HMMA(acc[6],  a1[0],a1[1],a1[2],a1[3], b1h[0],b1h[1]);
        HMMA(acc[7],  a1[0],a1[1],a1[2],a1[3], b1h[2],b1h[3]);
        HMMA(acc[8],  a2[0],a2[1],a2[2],a2[3], b0h[0],b0h[1]);
        HMMA(acc[9],  a2[0],a2[1],a2[2],a2[3], b0h[2],b0h[3]);
        HMMA(acc[10], a2[0],a2[1],a2[2],a2[3], b1h[0],b1h[1]);
        HMMA(acc[11], a2[0],a2[1],a2[2],a2[3], b1h[2],b1h[3]);
        HMMA(acc[12], a3[0],a3[1],a3[2],a3[3], b0h[0],b0h[1]);
        HMMA(acc[13], a3[0],a3[1],a3[2],a3[3], b0h[2],b0h[3]);
        HMMA(acc[14], a3[0],a3[1],a3[2],a3[3], b1h[0],b1h[1]);
        HMMA(acc[15], a3[0],a3[1],a3[2],a3[3], b1h[2],b1h[3]);

        HMMA(acc[0],  a0[0],a0[1],a0[2],a0[3], b0l[0],b0l[1]);
        HMMA(acc[1],  a0[0],a0[1],a0[2],a0[3], b0l[2],b0l[3]);
        HMMA(acc[2],  a0[0],a0[1],a0[2],a0[3], b1l[0],b1l[1]);
        HMMA(acc[3],  a0[0],a0[1],a0[2],a0[3], b1l[2],b1l[3]);
        HMMA(acc[4],  a1[0],a1[1],a1[2],a1[3], b0l[0],b0l[1]);
        HMMA(acc[5],  a1[0],a1[1],a1[2],a1[3], b0l[2],b0l[3]);
        HMMA(acc[6],  a1[0],a1[1],a1[2],a1[3], b1l[0],b1l[1]);
        HMMA(acc[7],  a1[0],a1[1],a1[2],a1[3], b1l[2],b1l[3]);
        HMMA(acc[8],  a2[0],a2[1],a2[2],a2[3], b0l[0],b0l[1]);
        HMMA(acc[9],  a2[0],a2[1],a2[2],a2[3], b0l[2],b0l[3]);
        HMMA(acc[10], a2[0],a2[1],a2[2],a2[3], b1l[0],b1l[1]);
        HMMA(acc[11], a2[0],a2[1],a2[2],a2[3], b1l[2],b1l[3]);
        HMMA(acc[12], a3[0],a3[1],a3[2],a3[3], b0l[0],b0l[1]);
        HMMA(acc[13], a3[0],a3[1],a3[2],a3[3], b0l[2],b0l[3]);
        HMMA(acc[14], a3[0],a3[1],a3[2],a3[3], b1l[0],b1l[1]);
        HMMA(acc[15], a3[0],a3[1],a3[2],a3[3], b1l[2],b1l[3]);

        // reload a <- lo plane (after last hi use), term2: a_lo x b_hi
        LDSM4(a0, stA + aOff + 8192);
        LDSM4(a1, stA + aOff + 8192 + 2048);
        LDSM4(a2, stA + aOff + 8192 + 4096);
        LDSM4(a3, stA + aOff + 8192 + 6144);

        HMMA(acc[0],  a0[0],a0[1],a0[2],a0[3], b0h[0],b0h[1]);
        HMMA(acc[1],  a0[0],a0[1],a0[2],a0[3], b0h[2],b0h[3]);
        HMMA(acc[2],  a0[0],a0[1],a0[2],a0[3], b1h[0],b1h[1]);
        HMMA(acc[3],  a0[0],a0[1],a0[2],a0[3], b1h[2],b1h[3]);
        HMMA(acc[4],  a1[0],a1[1],a1[2],a1[3], b0h[0],b0h[1]);
        HMMA(acc[5],  a1[0],a1[1],a1[2],a1[3], b0h[2],b0h[3]);
        HMMA(acc[6],  a1[0],a1[1],a1[2],a1[3], b1h[0],b1h[1]);
        HMMA(acc[7],  a1[0],a1[1],a1[2],a1[3], b1h[2],b1h[3]);
        HMMA(acc[8],  a2[0],a2[1],a2[2],a2[3], b0h[0],b0h[1]);
        HMMA(acc[9],  a2[0],a2[1],a2[2],a2[3], b0h[2],b0h[3]);
        HMMA(acc[10], a2[0],a2[1],a2[2],a2[3], b1h[0],b1h[1]);
        HMMA(acc[11], a2[0],a2[1],a2[2],a2[3], b1h[2],b1h[3]);
        HMMA(acc[12], a3[0],a3[1],a3[2],a3[3], b0h[0],b0h[1]);
        HMMA(acc[13], a3[0],a3[1],a3[2],a3[3], b0h[2],b0h[3]);
        HMMA(acc[14], a3[0],a3[1],a3[2],a3[3], b1h[0],b1h[1]);
        HMMA(acc[15], a3[0],a3[1],a3[2],a3[3], b1h[2],b1h[3]);
    }

    // ---------------- epilogue: 8 partials -> fused LSTM cell -------------
    __syncthreads();                      // all stages consumed; overlay gb
    float* gb = (float*)smem;             // [8 partial][64 m][66]
    {
        float* myb = gb + (grp * 4 + sub) * (64 * 66);
        const int mrow = lane >> 2;
        const int ncol = 2 * (lane & 3);
#pragma unroll
        for (int i = 0; i < 16; i++) {
            const int mt = i >> 2, n8 = i & 3;
            const int m = mt * 16 + mrow;
            const int n = half * 32 + n8 * 8 + ncol;
            *(float2*)&gb[(grp * 4 + sub) * (64 * 66) + m * 66 + n] =
                make_float2(acc[i][0], acc[i][1]);
            *(float2*)&myb[(m + 8) * 66 + n] = make_float2(acc[i][2], acc[i][3]);
        }
    }
    __syncthreads();

    // 512 threads x 2 cells: CTA covers 16 j (two 32-row perm blocks) x 64 b
#pragma unroll
    for (int k = 0; k < 2; k++) {
        const int c   = tid + k * 512;    // 0..1023
        const int b   = c >> 4;
        const int jl2 = c & 15;
        const int rowbase = (jl2 < 8) ? 0 : 32;
        const int jj  = jl2 & 7;
        const int j   = mblk * 16 + jl2;
        float gsum[4];
#pragma unroll
        for (int g = 0; g < 4; g++) {
            const int m = rowbase + g * 8 + jj;
            float s = 0.f;
#pragma unroll
            for (int pp = 0; pp < 8; pp++)
                s += gb[(pp * 64 + m) * 66 + b];
            gsum[g] = s;
        }
        float gi = gsum[0] + bs[j];
        float gf = gsum[1] + bs[1024 + j];
        float gg = gsum[2] + bs[2048 + j];
        float go = gsum[3] + bs[3072 + j];
        float cn = sigm(gf) * Cl[b * Hh + j] + sigm(gi) * tanh_(gg);
        Cl[b * Hh + j] = cn;
        float hn = sigm(go) * tanh_(cn);
        __nv_bfloat16 hi = __float2bfloat16(hn);
        o_hi[b * Hh + j] = hi;
        o_lo[b * Hh + j] = __float2bfloat16(hn - __bfloat162float(hi));
        if (role == 1 && tt == Tt - 1) Hf[b * Hh + j] = hn;
    }
}

// ---------------- host launcher ----------------
extern "C" void kernel_launch(void* const* d_in, const int* in_sizes, int n_in,
                              void* d_out, int out_size) {
    const float* x_seq = (const float*)d_in[0];
    const float* h0    = (const float*)d_in[1];
    const float* c0    = (const float*)d_in[2];
    const float* Wih   = (const float*)d_in[3];
    const float* Whh   = (const float*)d_in[4];
    const float* bih   = (const float*)d_in[5];
    const float* bhh   = (const float*)d_in[6];

    cudaFuncSetAttribute(lstm_wave,
                         cudaFuncAttributeMaxDynamicSharedMemorySize, SMEM_TOTAL);

    void *p_xhi, *p_xlo, *p_w, *p_bs, *p_hhi, *p_hlo, *p_c, *p_hf;
    cudaGetSymbolAddress(&p_xhi, g_xhi);
    cudaGetSymbolAddress(&p_xlo, g_xlo);
    cudaGetSymbolAddress(&p_w,   g_W);
    cudaGetSymbolAddress(&p_bs,  g_bsum);
    cudaGetSymbolAddress(&p_hhi, g_Hhi);
    cudaGetSymbolAddress(&p_hlo, g_Hlo);
    cudaGetSymbolAddress(&p_c,   g_C);
    cudaGetSymbolAddress(&p_hf,  g_Hf);

    split_x_kernel<<<8192, 256>>>(x_seq, Tt * BH);
    init_state_kernel<<<512, 256>>>(h0, c0, bih, bhh);
    prep_w_kernel<<<8192, 256>>>(Wih, Whh);

    for (int w = 0; w <= Tt; w++) {
        lstm_wave<<<128, 512, SMEM_TOTAL>>>(
            (const __nv_bfloat16*)p_w, (const float*)p_bs,
            (const __nv_bfloat16*)p_xhi, (const __nv_bfloat16*)p_xlo,
            (__nv_bfloat16*)p_hhi, (__nv_bfloat16*)p_hlo,
            (float*)p_c, (float*)p_hf, w);
    }
    cudaMemcpyAsync(d_out, p_hf, (size_t)BH * sizeof(float),
                    cudaMemcpyDeviceToDevice);
}

// round 12
// speedup vs baseline: 1.5171x; 1.1884x over previous
#include <cuda_runtime.h>
#include <cuda_fp16.h>
#include <cstdint>

// StackLSTM T=256, B=64, H=1024, L=2 — Round 12 (R11 + macro-collision fix).
// fp16 2-term W-split (gates = a@w_hi + a@w_lo, a single fp16, fp32 acc).
// At ~95% of the legacy mma.sync roofline the only win is fewer HMMA:
// 48 -> 32 per chunk (x2/3) and halved B traffic. Wave fusion kept from R10.

#define Tt 256
#define Bb 64
#define Hh 1024
#define BH (Bb * Hh)                 // 65536
#define M4H 4096
#define KK 2048
#define WPL (2ULL * M4H * KK)        // fp16 elems per layer (hi+lo planes)
#define STAGE 24576                  // A 16KB (hi+lo) + B 8KB (single plane)
#define NSTAGE 3
#define GSZ (NSTAGE * STAGE)         // 73728 per group
#define SMEM_TOTAL (2 * GSZ)         // 147456

// ---------------- persistent device state ----------------
__device__ __half g_xh[Tt * BH];             // input seq, fp16
__device__ __half g_W[2 * WPL];              // [layer][hl][4096 perm rows][2048]
__device__ float  g_bsum[2 * M4H];
__device__ __half g_Hh[2 * 2 * BH];          // [layer][parity][BH], fp16
__device__ float  g_C[2 * BH];
__device__ float  g_Hf[BH];                  // final top-layer hidden (fp32)

// ---------------- helpers ----------------
__device__ __forceinline__ uint32_t smem_u32(const void* p) {
    uint32_t a;
    asm("{ .reg .u64 t; cvta.to.shared.u64 t, %1; cvt.u32.u64 %0, t; }"
        : "=r"(a) : "l"(p));
    return a;
}
__device__ __forceinline__ void cp16(uint32_t d, const void* g) {
    asm volatile("cp.async.cg.shared.global [%0], [%1], 16;"
                 :: "r"(d), "l"(g) : "memory");
}
#define CP_COMMIT() asm volatile("cp.async.commit_group;" ::: "memory")
#define CP_WAIT1()  asm volatile("cp.async.wait_group 1;" ::: "memory")
#define CP_WAIT0()  asm volatile("cp.async.wait_group 0;" ::: "memory")

#define LDSM4(r, addr) \
    asm volatile("ldmatrix.sync.aligned.m8n8.x4.shared.b16 {%0,%1,%2,%3}, [%4];" \
        : "=r"((r)[0]), "=r"((r)[1]), "=r"((r)[2]), "=r"((r)[3]) : "r"(addr))

#define HMMA(d, a0, a1, a2, a3, b0, b1) \
    asm volatile("mma.sync.aligned.m16n8k16.row.col.f32.f16.f16.f32 " \
        "{%0,%1,%2,%3},{%4,%5,%6,%7},{%8,%9},{%0,%1,%2,%3};" \
        : "+f"((d)[0]), "+f"((d)[1]), "+f"((d)[2]), "+f"((d)[3]) \
        : "r"(a0), "r"(a1), "r"(a2), "r"(a3), "r"(b0), "r"(b1))

__device__ __forceinline__ void gbar(int grp) {
    if (grp == 0) asm volatile("bar.sync 1, 256;" ::: "memory");
    else          asm volatile("bar.sync 2, 256;" ::: "memory");
}

__device__ __forceinline__ float sigm(float x) { return 1.0f / (1.0f + __expf(-x)); }
__device__ __forceinline__ float tanh_(float x) {
    float ax = fabsf(x);
    float e  = __expf(-2.0f * ax);
    return copysignf((1.0f - e) / (1.0f + e), x);
}

// ---------------- prep kernels ----------------
__global__ void split_x_kernel(const float* __restrict__ x, int n) {
    for (int i = blockIdx.x * blockDim.x + threadIdx.x; i < n;
         i += gridDim.x * blockDim.x)
        g_xh[i] = __float2half(x[i]);
}

__global__ void init_state_kernel(const float* __restrict__ h0,
                                  const float* __restrict__ c0,
                                  const float* __restrict__ bih,
                                  const float* __restrict__ bhh) {
    int t0 = blockIdx.x * blockDim.x + threadIdx.x;
    for (int idx = t0; idx < 2 * BH; idx += gridDim.x * blockDim.x) {
        int l = idx / BH, r = idx % BH;
        g_Hh[(l * 2 + 0) * BH + r] = __float2half(h0[idx]);
        g_C[idx] = c0[idx];
    }
    for (int idx = t0; idx < 2 * M4H; idx += gridDim.x * blockDim.x)
        g_bsum[idx] = bih[idx] + bhh[idx];
}

// g_W[l][hl][p][k]: permuted row p: blk=p>>5 (32-row perm block), lcl=p&31,
// gate=lcl>>3, jl=lcl&7, j=blk*8+jl, src row=gate*1024+j. k<1024->Wih else Whh.
__global__ void prep_w_kernel(const float* __restrict__ Wih,
                              const float* __restrict__ Whh) {
    const long long per = (long long)M4H * KK;
    const long long n   = 2 * 2 * per;
    for (long long idx = blockIdx.x * (long long)blockDim.x + threadIdx.x; idx < n;
         idx += (long long)gridDim.x * blockDim.x) {
        int  l  = (int)(idx / (2 * per));
        long long r1 = idx % (2 * per);
        int  hl = (int)(r1 / per);
        long long r2 = r1 % per;
        int  p  = (int)(r2 / KK), k = (int)(r2 % KK);
        int  blk = p >> 5, lcl = p & 31;
        int  gate = lcl >> 3, jl = lcl & 7;
        int  j = blk * 8 + jl;
        int  srow = gate * 1024 + j;
        float w = (k < 1024)
                ? Wih[(size_t)l * M4H * Hh + (size_t)srow * Hh + k]
                : Whh[(size_t)l * M4H * Hh + (size_t)srow * Hh + (k - 1024)];
        __half hi = __float2half(w);
        g_W[idx] = hl ? __float2half(w - __half2float(hi)) : hi;
    }
}

// ---------------- wave kernel: layer0[w] || layer1[w-1] ----------------
// grid = 128: blocks 0..63 role 0 (layer0, M64 tile mblk), 64..127 role 1.
// block = 512 = 2 K-split groups x 8 warps; warp: sub = k16 slot, half = N32.
// Warp tile M64 x N32: per chunk 10 LDSM.x4, 32 HMMA (2 fp16 terms).
__global__ void __launch_bounds__(512, 1) lstm_wave(
    const __half* __restrict__ W,
    const float*  __restrict__ bsum,
    const __half* __restrict__ xh,
    __half* __restrict__ Hbuf,
    float* __restrict__ Cst,
    float* __restrict__ Hfin,
    int w)
{
    const int role = blockIdx.x >> 6;
    const int mblk = blockIdx.x & 63;
    if (role == 0 && w >= Tt) return;
    if (role == 1 && w == 0)  return;

    const int tt = role ? (w - 1) : w;
    const int p  = tt & 1;

    const __half *xs, *hs;
    __half *o_h;
    const __half* Wl;
    const float* bs;
    float* Cl;
    if (role == 0) {
        xs  = xh + (size_t)tt * BH;
        hs  = Hbuf + (size_t)p * BH;
        o_h = Hbuf + (size_t)(p ^ 1) * BH;
        Wl = W; bs = bsum; Cl = Cst;
    } else {
        xs  = Hbuf + (size_t)(p ^ 1) * BH;      // layer0 fresh hidden @ tt
        hs  = Hbuf + (size_t)(2 + p) * BH;
        o_h = Hbuf + (size_t)(2 + (p ^ 1)) * BH;
        Wl = W + WPL; bs = bsum + M4H; Cl = Cst + BH;
    }

    extern __shared__ char smem[];
    const int tid  = threadIdx.x;
    const int grp  = tid >> 8;           // K-split group: 0 -> x half, 1 -> h half
    const int gtid = tid & 255;
    const int gwid = gtid >> 5, lane = tid & 31;
    const int sub  = gwid >> 1;          // k16 index within K64 chunk
    const int half = gwid & 1;           // N32 half
    const uint32_t sb = smem_u32(smem) + grp * GSZ;

    // fragment addressing (swizzled smem, 128B rows)
    const int rA  = lane & 15;
    const int rB  = (lane & 7) + ((lane >> 4) << 3);
    const uint32_t qa = 2 * sub + (lane >> 4);
    const uint32_t qb = 2 * sub + ((lane >> 3) & 1);
    const uint32_t aOff = rA * 128 + (((qa ^ (rA & 7))) << 4);
    const uint32_t bOff = (half * 32 + rB) * 128 + (((qb ^ (rB & 7))) << 4);

    const __half* b_src = grp ? hs : xs;
    const __half* Wbase = Wl + (size_t)(mblk * 64) * KK + grp * 1024;

    // M64xN32 accumulators: acc[mt*4 + n8]
    float acc[16][4];
#pragma unroll
    for (int i = 0; i < 16; i++)
#pragma unroll
        for (int r = 0; r < 4; r++) acc[i][r] = 0.f;

    auto load_chunk = [&](int lc) {
        const int st = lc % 3;
        const uint32_t stA = sb + st * STAGE;
        const uint32_t stB = stA + 16384;
        const int koff = lc * 64;
        // A: [2 hl][64 rows][8 q] = 1024 16B units; 4/thread
#pragma unroll
        for (int i = 0; i < 4; i++) {
            int u = gtid + i * 256;
            int hl = u >> 9, rem = u & 511, row = rem >> 3, q = rem & 7;
            const __half* s = Wbase + (size_t)hl * (M4H * KK)
                            + (size_t)row * KK + koff + q * 8;
            cp16(stA + hl * 8192 + row * 128 + ((q ^ (row & 7)) << 4), s);
        }
        // B: [64 rows][8 q] = 512 units; 2/thread (single fp16 plane)
#pragma unroll
        for (int i = 0; i < 2; i++) {
            int u = gtid + i * 256;
            int row = u >> 3, q = u & 7;
            const __half* s = b_src + (size_t)row * 1024 + koff + q * 8;
            cp16(stB + row * 128 + ((q ^ (row & 7)) << 4), s);
        }
        CP_COMMIT();
    };

    load_chunk(0);
    load_chunk(1);

    for (int lc = 0; lc < 16; ++lc) {
        if (lc <= 14) CP_WAIT1();
        else          CP_WAIT0();
        gbar(grp);
        if (lc + 2 < 16) load_chunk(lc + 2);

        const uint32_t stA = sb + (lc % 3) * STAGE;
        const uint32_t stB = stA + 16384;

        uint32_t a0[4], a1[4], a2[4], a3[4];
        uint32_t b0[4], b1[4];
        LDSM4(a0, stA + aOff);                  // w_hi plane, m-tiles 0..3
        LDSM4(a1, stA + aOff + 2048);
        LDSM4(a2, stA + aOff + 4096);
        LDSM4(a3, stA + aOff + 6144);
        LDSM4(b0, stB + bOff);                  // activations (single plane)
        LDSM4(b1, stB + bOff + 2048);

        // term 0: w_hi x a
        HMMA(acc[0],  a0[0],a0[1],a0[2],a0[3], b0[0],b0[1]);
        HMMA(acc[1],  a0[0],a0[1],a0[2],a0[3], b0[2],b0[3]);
        HMMA(acc[2],  a0[0],a0[1],a0[2],a0[3], b1[0],b1[1]);
        HMMA(acc[3],  a0[0],a0[1],a0[2],a0[3], b1[2],b1[3]);
        HMMA(acc[4],  a1[0],a1[1],a1[2],a1[3], b0[0],b0[1]);
        HMMA(acc[5],  a1[0],a1[1],a1[2],a1[3], b0[2],b0[3]);
        HMMA(acc[6],  a1[0],a1[1],a1[2],a1[3], b1[0],b1[1]);
        HMMA(acc[7],  a1[0],a1[1],a1[2],a1[3], b1[2],b1[3]);
        HMMA(acc[8],  a2[0],a2[1],a2[2],a2[3], b0[0],b0[1]);
        HMMA(acc[9],  a2[0],a2[1],a2[2],a2[3], b0[2],b0[3]);
        HMMA(acc[10], a2[0],a2[1],a2[2],a2[3], b1[0],b1[1]);
        HMMA(acc[11], a2[0],a2[1],a2[2],a2[3], b1[2],b1[3]);
        HMMA(acc[12], a3[0],a3[1],a3[2],a3[3], b0[0],b0[1]);
        HMMA(acc[13], a3[0],a3[1],a3[2],a3[3], b0[2],b0[3]);
        HMMA(acc[14], a3[0],a3[1],a3[2],a3[3], b1[0],b1[1]);
        HMMA(acc[15], a3[0],a3[1],a3[2],a3[3], b1[2],b1[3]);

        // reload a <- w_lo plane, term 1: w_lo x a
        LDSM4(a0, stA + aOff + 8192);
        LDSM4(a1, stA + aOff + 8192 + 2048);
        LDSM4(a2, stA + aOff + 8192 + 4096);
        LDSM4(a3, stA + aOff + 8192 + 6144);

        HMMA(acc[0],  a0[0],a0[1],a0[2],a0[3], b0[0],b0[1]);
        HMMA(acc[1],  a0[0],a0[1],a0[2],a0[3], b0[2],b0[3]);
        HMMA(acc[2],  a0[0],a0[1],a0[2],a0[3], b1[0],b1[1]);
        HMMA(acc[3],  a0[0],a0[1],a0[2],a0[3], b1[2],b1[3]);
        HMMA(acc[4],  a1[0],a1[1],a1[2],a1[3], b0[0],b0[1]);
        HMMA(acc[5],  a1[0],a1[1],a1[2],a1[3], b0[2],b0[3]);
        HMMA(acc[6],  a1[0],a1[1],a1[2],a1[3], b1[0],b1[1]);
        HMMA(acc[7],  a1[0],a1[1],a1[2],a1[3], b1[2],b1[3]);
        HMMA(acc[8],  a2[0],a2[1],a2[2],a2[3], b0[0],b0[1]);
        HMMA(acc[9],  a2[0],a2[1],a2[2],a2[3], b0[2],b0[3]);
        HMMA(acc[10], a2[0],a2[1],a2[2],a2[3], b1[0],b1[1]);
        HMMA(acc[11], a2[0],a2[1],a2[2],a2[3], b1[2],b1[3]);
        HMMA(acc[12], a3[0],a3[1],a3[2],a3[3], b0[0],b0[1]);
        HMMA(acc[13], a3[0],a3[1],a3[2],a3[3], b0[2],b0[3]);
        HMMA(acc[14], a3[0],a3[1],a3[2],a3[3], b1[0],b1[1]);
        HMMA(acc[15], a3[0],a3[1],a3[2],a3[3], b1[2],b1[3]);
    }

    // ---------------- epilogue: 8 partials -> fused LSTM cell -------------
    __syncthreads();                      // all stages consumed; overlay gb
    float* gb = (float*)smem;             // [8 partial][64 m][66] = 135168 B
    {
        float* myb = gb + (grp * 4 + sub) * (64 * 66);
        const int mrow = lane >> 2;
        const int ncol = 2 * (lane & 3);
#pragma unroll
        for (int i = 0; i < 16; i++) {
            const int mt = i >> 2, n8 = i & 3;
            const int m = mt * 16 + mrow;
            const int n = half * 32 + n8 * 8 + ncol;
            *(float2*)&myb[m * 66 + n]       = make_float2(acc[i][0], acc[i][1]);
            *(float2*)&myb[(m + 8) * 66 + n] = make_float2(acc[i][2], acc[i][3]);
        }
    }
    __syncthreads();

    // 512 threads x 2 cells: CTA covers 16 j (two 32-row perm blocks) x 64 b
#pragma unroll
    for (int k = 0; k < 2; k++) {
        const int c   = tid + k * 512;    // 0..1023
        const int b   = c >> 4;
        const int jl2 = c & 15;
        const int rowbase = (jl2 < 8) ? 0 : 32;
        const int jj  = jl2 & 7;
        const int j   = mblk * 16 + jl2;
        float gsum[4];
#pragma unroll
        for (int g = 0; g < 4; g++) {
            const int m = rowbase + g * 8 + jj;
            float s = 0.f;
#pragma unroll
            for (int pp = 0; pp < 8; pp++)
                s += gb[(pp * 64 + m) * 66 + b];
            gsum[g] = s;
        }
        float gi = gsum[0] + bs[j];
        float gf = gsum[1] + bs[1024 + j];
        float gg = gsum[2] + bs[2048 + j];
        float go = gsum[3] + bs[3072 + j];
        float cn = sigm(gf) * Cl[b * Hh + j] + sigm(gi) * tanh_(gg);
        Cl[b * Hh + j] = cn;
        float hn = sigm(go) * tanh_(cn);
        o_h[b * Hh + j] = __float2half(hn);
        if (role == 1 && tt == Tt - 1) Hfin[b * Hh + j] = hn;
    }
}

// ---------------- host launcher ----------------
extern "C" void kernel_launch(void* const* d_in, const int* in_sizes, int n_in,
                              void* d_out, int out_size) {
    const float* x_seq = (const float*)d_in[0];
    const float* h0    = (const float*)d_in[1];
    const float* c0    = (const float*)d_in[2];
    const float* Wih   = (const float*)d_in[3];
    const float* Whh   = (const float*)d_in[4];
    const float* bih   = (const float*)d_in[5];
    const float* bhh   = (const float*)d_in[6];

    cudaFuncSetAttribute(lstm_wave,
                         cudaFuncAttributeMaxDynamicSharedMemorySize, SMEM_TOTAL);

    void *p_xh, *p_w, *p_bs, *p_hh, *p_c, *p_hf;
    cudaGetSymbolAddress(&p_xh, g_xh);
    cudaGetSymbolAddress(&p_w,  g_W);
    cudaGetSymbolAddress(&p_bs, g_bsum);
    cudaGetSymbolAddress(&p_hh, g_Hh);
    cudaGetSymbolAddress(&p_c,  g_C);
    cudaGetSymbolAddress(&p_hf, g_Hf);

    split_x_kernel<<<8192, 256>>>(x_seq, Tt * BH);
    init_state_kernel<<<512, 256>>>(h0, c0, bih, bhh);
    prep_w_kernel<<<8192, 256>>>(Wih, Whh);

    for (int w = 0; w <= Tt; w++) {
        lstm_wave<<<128, 512, SMEM_TOTAL>>>(
            (const __half*)p_w, (const float*)p_bs,
            (const __half*)p_xh,
            (__half*)p_hh, (float*)p_c, (float*)p_hf, w);
    }
    cudaMemcpyAsync(d_out, p_hf, (size_t)BH * sizeof(float),
                    cudaMemcpyDeviceToDevice);
}

// round 13
// speedup vs baseline: 2.2337x; 1.4724x over previous
#include <cuda_runtime.h>
#include <cuda_fp16.h>
#include <cstdint>

// StackLSTM T=256, B=64, H=1024, L=2 — Round 13.
// R13 = R12 with the w_lo correction term DROPPED: single fp16 weight plane,
// gates = a @ w (fp16 x fp16, fp32 accum). Halves HMMA (floor 16.4 -> 8.2 us
// per wave) and halves A traffic; weights (32 MB) fully L2-resident.
// Error model: + ~1.4e-4/step weight-rounding noise in quadrature with the
// measured 3.08e-4 activation noise -> ~4-5e-4 final (gate 1e-3).
// Wave fusion kept: layer0[w] || layer1[w-1], 128 CTAs, M64 tiles.

#define Tt 256
#define Bb 64
#define Hh 1024
#define BH (Bb * Hh)                 // 65536
#define M4H 4096
#define KK 2048
#define WPL ((size_t)M4H * KK)       // fp16 elems per layer (single plane)
#define STAGE 16384                  // A 8KB + B 8KB
#define NSTAGE 3
#define GSZ (NSTAGE * STAGE)         // 49152 per group
#define SMEM_TOTAL 135168            // epilogue buffer (8*64*66*4) dominates

// ---------------- persistent device state ----------------
__device__ __half g_xh[Tt * BH];             // input seq, fp16
__device__ __half g_W[2 * WPL];              // [layer][4096 perm rows][2048]
__device__ float  g_bsum[2 * M4H];
__device__ __half g_Hh[2 * 2 * BH];          // [layer][parity][BH], fp16
__device__ float  g_C[2 * BH];
__device__ float  g_Hf[BH];                  // final top-layer hidden (fp32)

// ---------------- helpers ----------------
__device__ __forceinline__ uint32_t smem_u32(const void* p) {
    uint32_t a;
    asm("{ .reg .u64 t; cvta.to.shared.u64 t, %1; cvt.u32.u64 %0, t; }"
        : "=r"(a) : "l"(p));
    return a;
}
__device__ __forceinline__ void cp16(uint32_t d, const void* g) {
    asm volatile("cp.async.cg.shared.global [%0], [%1], 16;"
                 :: "r"(d), "l"(g) : "memory");
}
#define CP_COMMIT() asm volatile("cp.async.commit_group;" ::: "memory")
#define CP_WAIT1()  asm volatile("cp.async.wait_group 1;" ::: "memory")
#define CP_WAIT0()  asm volatile("cp.async.wait_group 0;" ::: "memory")

#define LDSM4(r, addr) \
    asm volatile("ldmatrix.sync.aligned.m8n8.x4.shared.b16 {%0,%1,%2,%3}, [%4];" \
        : "=r"((r)[0]), "=r"((r)[1]), "=r"((r)[2]), "=r"((r)[3]) : "r"(addr))

#define HMMA(d, a0, a1, a2, a3, b0, b1) \
    asm volatile("mma.sync.aligned.m16n8k16.row.col.f32.f16.f16.f32 " \
        "{%0,%1,%2,%3},{%4,%5,%6,%7},{%8,%9},{%0,%1,%2,%3};" \
        : "+f"((d)[0]), "+f"((d)[1]), "+f"((d)[2]), "+f"((d)[3]) \
        : "r"(a0), "r"(a1), "r"(a2), "r"(a3), "r"(b0), "r"(b1))

__device__ __forceinline__ void gbar(int grp) {
    if (grp == 0) asm volatile("bar.sync 1, 256;" ::: "memory");
    else          asm volatile("bar.sync 2, 256;" ::: "memory");
}

__device__ __forceinline__ float sigm(float x) { return 1.0f / (1.0f + __expf(-x)); }
__device__ __forceinline__ float tanh_(float x) {
    float ax = fabsf(x);
    float e  = __expf(-2.0f * ax);
    return copysignf((1.0f - e) / (1.0f + e), x);
}

// ---------------- prep kernels ----------------
__global__ void split_x_kernel(const float* __restrict__ x, int n) {
    for (int i = blockIdx.x * blockDim.x + threadIdx.x; i < n;
         i += gridDim.x * blockDim.x)
        g_xh[i] = __float2half(x[i]);
}

__global__ void init_state_kernel(const float* __restrict__ h0,
                                  const float* __restrict__ c0,
                                  const float* __restrict__ bih,
                                  const float* __restrict__ bhh) {
    int t0 = blockIdx.x * blockDim.x + threadIdx.x;
    for (int idx = t0; idx < 2 * BH; idx += gridDim.x * blockDim.x) {
        int l = idx / BH, r = idx % BH;
        g_Hh[(l * 2 + 0) * BH + r] = __float2half(h0[idx]);
        g_C[idx] = c0[idx];
    }
    for (int idx = t0; idx < 2 * M4H; idx += gridDim.x * blockDim.x)
        g_bsum[idx] = bih[idx] + bhh[idx];
}

// g_W[l][p][k]: permuted row p: blk=p>>5 (32-row perm block), lcl=p&31,
// gate=lcl>>3, jl=lcl&7, j=blk*8+jl, src row=gate*1024+j. k<1024->Wih else Whh.
__global__ void prep_w_kernel(const float* __restrict__ Wih,
                              const float* __restrict__ Whh) {
    const long long per = (long long)M4H * KK;
    const long long n   = 2 * per;
    for (long long idx = blockIdx.x * (long long)blockDim.x + threadIdx.x; idx < n;
         idx += (long long)gridDim.x * blockDim.x) {
        int  l  = (int)(idx / per);
        long long r2 = idx % per;
        int  p  = (int)(r2 / KK), k = (int)(r2 % KK);
        int  blk = p >> 5, lcl = p & 31;
        int  gate = lcl >> 3, jl = lcl & 7;
        int  j = blk * 8 + jl;
        int  srow = gate * 1024 + j;
        float w = (k < 1024)
                ? Wih[(size_t)l * M4H * Hh + (size_t)srow * Hh + k]
                : Whh[(size_t)l * M4H * Hh + (size_t)srow * Hh + (k - 1024)];
        g_W[idx] = __float2half(w);
    }
}

// ---------------- wave kernel: layer0[w] || layer1[w-1] ----------------
// grid = 128: blocks 0..63 role 0 (layer0, M64 tile mblk), 64..127 role 1.
// block = 512 = 2 K-split groups x 8 warps; warp: sub = k16 slot, half = N32.
// Warp tile M64 x N32: per chunk 6 LDSM.x4, 16 HMMA (single fp16 term).
__global__ void __launch_bounds__(512, 1) lstm_wave(
    const __half* __restrict__ W,
    const float*  __restrict__ bsum,
    const __half* __restrict__ xh,
    __half* __restrict__ Hbuf,
    float* __restrict__ Cst,
    float* __restrict__ Hfin,
    int w)
{
    const int role = blockIdx.x >> 6;
    const int mblk = blockIdx.x & 63;
    if (role == 0 && w >= Tt) return;
    if (role == 1 && w == 0)  return;

    const int tt = role ? (w - 1) : w;
    const int p  = tt & 1;

    const __half *xs, *hs;
    __half *o_h;
    const __half* Wl;
    const float* bs;
    float* Cl;
    if (role == 0) {
        xs  = xh + (size_t)tt * BH;
        hs  = Hbuf + (size_t)p * BH;
        o_h = Hbuf + (size_t)(p ^ 1) * BH;
        Wl = W; bs = bsum; Cl = Cst;
    } else {
        xs  = Hbuf + (size_t)(p ^ 1) * BH;      // layer0 fresh hidden @ tt
        hs  = Hbuf + (size_t)(2 + p) * BH;
        o_h = Hbuf + (size_t)(2 + (p ^ 1)) * BH;
        Wl = W + WPL; bs = bsum + M4H; Cl = Cst + BH;
    }

    extern __shared__ char smem[];
    const int tid  = threadIdx.x;
    const int grp  = tid >> 8;           // K-split group: 0 -> x half, 1 -> h half
    const int gtid = tid & 255;
    const int gwid = gtid >> 5, lane = tid & 31;
    const int sub  = gwid >> 1;          // k16 index within K64 chunk
    const int half = gwid & 1;           // N32 half
    const uint32_t sb = smem_u32(smem) + grp * GSZ;

    // fragment addressing (swizzled smem, 128B rows)
    const int rA  = lane & 15;
    const int rB  = (lane & 7) + ((lane >> 4) << 3);
    const uint32_t qa = 2 * sub + (lane >> 4);
    const uint32_t qb = 2 * sub + ((lane >> 3) & 1);
    const uint32_t aOff = rA * 128 + (((qa ^ (rA & 7))) << 4);
    const uint32_t bOff = rB * 128 + (((qb ^ (rB & 7))) << 4);

    const __half* b_src = (grp ? hs : xs) + (size_t)(half * 32) * Hh;
    const __half* Wbase = Wl + (size_t)(mblk * 64) * KK + grp * 1024;

    // M64xN32 accumulators: acc[mt*4 + n8]
    float acc[16][4];
#pragma unroll
    for (int i = 0; i < 16; i++)
#pragma unroll
        for (int r = 0; r < 4; r++) acc[i][r] = 0.f;

    auto load_chunk = [&](int lc) {
        const int st = lc % 3;
        const uint32_t stA = sb + st * STAGE;
        const uint32_t stB = stA + 8192;
        const int koff = lc * 64;
        // A: [64 rows][8 q] = 512 16B units; 2/thread
#pragma unroll
        for (int i = 0; i < 2; i++) {
            int u = gtid + i * 256;
            int row = u >> 3, q = u & 7;
            const __half* s = Wbase + (size_t)row * KK + koff + q * 8;
            cp16(stA + row * 128 + ((q ^ (row & 7)) << 4), s);
        }
        // B: [64 rows][8 q] = 512 units; 2/thread
#pragma unroll
        for (int i = 0; i < 2; i++) {
            int u = gtid + i * 256;
            int row = u >> 3, q = u & 7;
            const __half* s = (grp ? hs : xs) + (size_t)row * Hh + koff + q * 8;
            cp16(stB + row * 128 + ((q ^ (row & 7)) << 4), s);
        }
        CP_COMMIT();
    };

    load_chunk(0);
    load_chunk(1);

    for (int lc = 0; lc < 16; ++lc) {
        if (lc <= 14) CP_WAIT1();
        else          CP_WAIT0();
        gbar(grp);
        if (lc + 2 < 16) load_chunk(lc + 2);

        const uint32_t stA = sb + (lc % 3) * STAGE;
        const uint32_t stB = stA + 8192;
        const uint32_t bO  = stB + half * 4096 + bOff;   // rows half*32 + rB

        uint32_t a0[4], a1[4], a2[4], a3[4];
        uint32_t b0[4], b1[4];
        LDSM4(a0, stA + aOff);                  // m-tiles 0..3
        LDSM4(a1, stA + aOff + 2048);
        LDSM4(a2, stA + aOff + 4096);
        LDSM4(a3, stA + aOff + 6144);
        LDSM4(b0, bO);                          // n-tiles of this N32 half
        LDSM4(b1, bO + 2048);

        HMMA(acc[0],  a0[0],a0[1],a0[2],a0[3], b0[0],b0[1]);
        HMMA(acc[1],  a0[0],a0[1],a0[2],a0[3], b0[2],b0[3]);
        HMMA(acc[2],  a0[0],a0[1],a0[2],a0[3], b1[0],b1[1]);
        HMMA(acc[3],  a0[0],a0[1],a0[2],a0[3], b1[2],b1[3]);
        HMMA(acc[4],  a1[0],a1[1],a1[2],a1[3], b0[0],b0[1]);
        HMMA(acc[5],  a1[0],a1[1],a1[2],a1[3], b0[2],b0[3]);
        HMMA(acc[6],  a1[0],a1[1],a1[2],a1[3], b1[0],b1[1]);
        HMMA(acc[7],  a1[0],a1[1],a1[2],a1[3], b1[2],b1[3]);
        HMMA(acc[8],  a2[0],a2[1],a2[2],a2[3], b0[0],b0[1]);
        HMMA(acc[9],  a2[0],a2[1],a2[2],a2[3], b0[2],b0[3]);
        HMMA(acc[10], a2[0],a2[1],a2[2],a2[3], b1[0],b1[1]);
        HMMA(acc[11], a2[0],a2[1],a2[2],a2[3], b1[2],b1[3]);
        HMMA(acc[12], a3[0],a3[1],a3[2],a3[3], b0[0],b0[1]);
        HMMA(acc[13], a3[0],a3[1],a3[2],a3[3], b0[2],b0[3]);
        HMMA(acc[14], a3[0],a3[1],a3[2],a3[3], b1[0],b1[1]);
        HMMA(acc[15], a3[0],a3[1],a3[2],a3[3], b1[2],b1[3]);
    }

    // ---------------- epilogue: 8 partials -> fused LSTM cell -------------
    __syncthreads();                      // all stages consumed; overlay gb
    float* gb = (float*)smem;             // [8 partial][64 m][66] = 135168 B
    {
        float* myb = gb + (grp * 4 + sub) * (64 * 66);
        const int mrow = lane >> 2;
        const int ncol = 2 * (lane & 3);
#pragma unroll
        for (int i = 0; i < 16; i++) {
            const int mt = i >> 2, n8 = i & 3;
            const int m = mt * 16 + mrow;
            const int n = half * 32 + n8 * 8 + ncol;
            *(float2*)&myb[m * 66 + n]       = make_float2(acc[i][0], acc[i][1]);
            *(float2*)&myb[(m + 8) * 66 + n] = make_float2(acc[i][2], acc[i][3]);
        }
    }
    __syncthreads();

    // 512 threads x 2 cells: CTA covers 16 j (two 32-row perm blocks) x 64 b
#pragma unroll
    for (int k = 0; k < 2; k++) {
        const int c   = tid + k * 512;    // 0..1023
        const int b   = c >> 4;
        const int jl2 = c & 15;
        const int rowbase = (jl2 < 8) ? 0 : 32;
        const int jj  = jl2 & 7;
        const int j   = mblk * 16 + jl2;
        float gsum[4];
#pragma unroll
        for (int g = 0; g < 4; g++) {
            const int m = rowbase + g * 8 + jj;
            float s = 0.f;
#pragma unroll
            for (int pp = 0; pp < 8; pp++)
                s += gb[(pp * 64 + m) * 66 + b];
            gsum[g] = s;
        }
        float gi = gsum[0] + bs[j];
        float gf = gsum[1] + bs[1024 + j];
        float gg = gsum[2] + bs[2048 + j];
        float go = gsum[3] + bs[3072 + j];
        float cn = sigm(gf) * Cl[b * Hh + j] + sigm(gi) * tanh_(gg);
        Cl[b * Hh + j] = cn;
        float hn = sigm(go) * tanh_(cn);
        o_h[b * Hh + j] = __float2half(hn);
        if (role == 1 && tt == Tt - 1) Hfin[b * Hh + j] = hn;
    }
}

// ---------------- host launcher ----------------
extern "C" void kernel_launch(void* const* d_in, const int* in_sizes, int n_in,
                              void* d_out, int out_size) {
    const float* x_seq = (const float*)d_in[0];
    const float* h0    = (const float*)d_in[1];
    const float* c0    = (const float*)d_in[2];
    const float* Wih   = (const float*)d_in[3];
    const float* Whh   = (const float*)d_in[4];
    const float* bih   = (const float*)d_in[5];
    const float* bhh   = (const float*)d_in[6];

    cudaFuncSetAttribute(lstm_wave,
                         cudaFuncAttributeMaxDynamicSharedMemorySize, SMEM_TOTAL);

    void *p_xh, *p_w, *p_bs, *p_hh, *p_c, *p_hf;
    cudaGetSymbolAddress(&p_xh, g_xh);
    cudaGetSymbolAddress(&p_w,  g_W);
    cudaGetSymbolAddress(&p_bs, g_bsum);
    cudaGetSymbolAddress(&p_hh, g_Hh);
    cudaGetSymbolAddress(&p_c,  g_C);
    cudaGetSymbolAddress(&p_hf, g_Hf);

    split_x_kernel<<<8192, 256>>>(x_seq, Tt * BH);
    init_state_kernel<<<512, 256>>>(h0, c0, bih, bhh);
    prep_w_kernel<<<8192, 256>>>(Wih, Whh);

    for (int w = 0; w <= Tt; w++) {
        lstm_wave<<<128, 512, SMEM_TOTAL>>>(
            (const __half*)p_w, (const float*)p_bs,
            (const __half*)p_xh,
            (__half*)p_hh, (float*)p_c, (float*)p_hf, w);
    }
    cudaMemcpyAsync(d_out, p_hf, (size_t)BH * sizeof(float),
                    cudaMemcpyDeviceToDevice);
}

// round 14
// speedup vs baseline: 2.2699x; 1.0162x over previous
#include <cuda_runtime.h>
#include <cuda_fp16.h>
#include <cstdint>

// StackLSTM T=256, B=64, H=1024, L=2 — Round 14.
// R14 = R13 (single fp16 plane, wave fusion) with K128 chunks:
// 8 iterations instead of 16 (half the barriers), each chunk = two k64
// sub-chunks in one stage; all 12 LDSM issued before the 32 HMMA so
// sub-chunk-1 loads overlap sub-chunk-0 tensor work (no barrier between).

#define Tt 256
#define Bb 64
#define Hh 1024
#define BH (Bb * Hh)                 // 65536
#define M4H 4096
#define KK 2048
#define WPL ((size_t)M4H * KK)       // fp16 elems per layer (single plane)
#define STAGE 32768                  // A 16KB (2 sub-tiles) + B 16KB
#define NSTAGE 3
#define GSZ (NSTAGE * STAGE)         // 98304 per group
#define SMEM_TOTAL (2 * GSZ)         // 196608 (epilogue 135168 overlays)

// ---------------- persistent device state ----------------
__device__ __half g_xh[Tt * BH];             // input seq, fp16
__device__ __half g_W[2 * WPL];              // [layer][4096 perm rows][2048]
__device__ float  g_bsum[2 * M4H];
__device__ __half g_Hh[2 * 2 * BH];          // [layer][parity][BH], fp16
__device__ float  g_C[2 * BH];
__device__ float  g_Hf[BH];                  // final top-layer hidden (fp32)

// ---------------- helpers ----------------
__device__ __forceinline__ uint32_t smem_u32(const void* p) {
    uint32_t a;
    asm("{ .reg .u64 t; cvta.to.shared.u64 t, %1; cvt.u32.u64 %0, t; }"
        : "=r"(a) : "l"(p));
    return a;
}
__device__ __forceinline__ void cp16(uint32_t d, const void* g) {
    asm volatile("cp.async.cg.shared.global [%0], [%1], 16;"
                 :: "r"(d), "l"(g) : "memory");
}
#define CP_COMMIT() asm volatile("cp.async.commit_group;" ::: "memory")
#define CP_WAIT1()  asm volatile("cp.async.wait_group 1;" ::: "memory")
#define CP_WAIT0()  asm volatile("cp.async.wait_group 0;" ::: "memory")

#define LDSM4(r, addr) \
    asm volatile("ldmatrix.sync.aligned.m8n8.x4.shared.b16 {%0,%1,%2,%3}, [%4];" \
        : "=r"((r)[0]), "=r"((r)[1]), "=r"((r)[2]), "=r"((r)[3]) : "r"(addr))

#define HMMA(d, a0, a1, a2, a3, b0, b1) \
    asm volatile("mma.sync.aligned.m16n8k16.row.col.f32.f16.f16.f32 " \
        "{%0,%1,%2,%3},{%4,%5,%6,%7},{%8,%9},{%0,%1,%2,%3};" \
        : "+f"((d)[0]), "+f"((d)[1]), "+f"((d)[2]), "+f"((d)[3]) \
        : "r"(a0), "r"(a1), "r"(a2), "r"(a3), "r"(b0), "r"(b1))

// 16 HMMA of one k64 sub-chunk: a-frags fa0..fa3, b-frags fb0, fb1
#define HMMA_BLOCK(fa0, fa1, fa2, fa3, fb0, fb1) do { \
    HMMA(acc[0],  fa0[0],fa0[1],fa0[2],fa0[3], fb0[0],fb0[1]); \
    HMMA(acc[1],  fa0[0],fa0[1],fa0[2],fa0[3], fb0[2],fb0[3]); \
    HMMA(acc[2],  fa0[0],fa0[1],fa0[2],fa0[3], fb1[0],fb1[1]); \
    HMMA(acc[3],  fa0[0],fa0[1],fa0[2],fa0[3], fb1[2],fb1[3]); \
    HMMA(acc[4],  fa1[0],fa1[1],fa1[2],fa1[3], fb0[0],fb0[1]); \
    HMMA(acc[5],  fa1[0],fa1[1],fa1[2],fa1[3], fb0[2],fb0[3]); \
    HMMA(acc[6],  fa1[0],fa1[1],fa1[2],fa1[3], fb1[0],fb1[1]); \
    HMMA(acc[7],  fa1[0],fa1[1],fa1[2],fa1[3], fb1[2],fb1[3]); \
    HMMA(acc[8],  fa2[0],fa2[1],fa2[2],fa2[3], fb0[0],fb0[1]); \
    HMMA(acc[9],  fa2[0],fa2[1],fa2[2],fa2[3], fb0[2],fb0[3]); \
    HMMA(acc[10], fa2[0],fa2[1],fa2[2],fa2[3], fb1[0],fb1[1]); \
    HMMA(acc[11], fa2[0],fa2[1],fa2[2],fa2[3], fb1[2],fb1[3]); \
    HMMA(acc[12], fa3[0],fa3[1],fa3[2],fa3[3], fb0[0],fb0[1]); \
    HMMA(acc[13], fa3[0],fa3[1],fa3[2],fa3[3], fb0[2],fb0[3]); \
    HMMA(acc[14], fa3[0],fa3[1],fa3[2],fa3[3], fb1[0],fb1[1]); \
    HMMA(acc[15], fa3[0],fa3[1],fa3[2],fa3[3], fb1[2],fb1[3]); \
} while (0)

__device__ __forceinline__ void gbar(int grp) {
    if (grp == 0) asm volatile("bar.sync 1, 256;" ::: "memory");
    else          asm volatile("bar.sync 2, 256;" ::: "memory");
}

__device__ __forceinline__ float sigm(float x) { return 1.0f / (1.0f + __expf(-x)); }
__device__ __forceinline__ float tanh_(float x) {
    float ax = fabsf(x);
    float e  = __expf(-2.0f * ax);
    return copysignf((1.0f - e) / (1.0f + e), x);
}

// ---------------- prep kernels ----------------
__global__ void split_x_kernel(const float* __restrict__ x, int n) {
    for (int i = blockIdx.x * blockDim.x + threadIdx.x; i < n;
         i += gridDim.x * blockDim.x)
        g_xh[i] = __float2half(x[i]);
}

__global__ void init_state_kernel(const float* __restrict__ h0,
                                  const float* __restrict__ c0,
                                  const float* __restrict__ bih,
                                  const float* __restrict__ bhh) {
    int t0 = blockIdx.x * blockDim.x + threadIdx.x;
    for (int idx = t0; idx < 2 * BH; idx += gridDim.x * blockDim.x) {
        int l = idx / BH, r = idx % BH;
        g_Hh[(l * 2 + 0) * BH + r] = __float2half(h0[idx]);
        g_C[idx] = c0[idx];
    }
    for (int idx = t0; idx < 2 * M4H; idx += gridDim.x * blockDim.x)
        g_bsum[idx] = bih[idx] + bhh[idx];
}

// g_W[l][p][k]: permuted row p: blk=p>>5 (32-row perm block), lcl=p&31,
// gate=lcl>>3, jl=lcl&7, j=blk*8+jl, src row=gate*1024+j. k<1024->Wih else Whh.
__global__ void prep_w_kernel(const float* __restrict__ Wih,
                              const float* __restrict__ Whh) {
    const long long per = (long long)M4H * KK;
    const long long n   = 2 * per;
    for (long long idx = blockIdx.x * (long long)blockDim.x + threadIdx.x; idx < n;
         idx += (long long)gridDim.x * blockDim.x) {
        int  l  = (int)(idx / per);
        long long r2 = idx % per;
        int  p  = (int)(r2 / KK), k = (int)(r2 % KK);
        int  blk = p >> 5, lcl = p & 31;
        int  gate = lcl >> 3, jl = lcl & 7;
        int  j = blk * 8 + jl;
        int  srow = gate * 1024 + j;
        float w = (k < 1024)
                ? Wih[(size_t)l * M4H * Hh + (size_t)srow * Hh + k]
                : Whh[(size_t)l * M4H * Hh + (size_t)srow * Hh + (k - 1024)];
        g_W[idx] = __float2half(w);
    }
}

// ---------------- wave kernel: layer0[w] || layer1[w-1] ----------------
// grid = 128: blocks 0..63 role 0 (layer0, M64 tile mblk), 64..127 role 1.
// block = 512 = 2 K-split groups x 8 warps; warp: sub = k16 slot, half = N32.
// Warp tile M64 x N32; per K128 chunk: 12 LDSM.x4 then 32 HMMA.
__global__ void __launch_bounds__(512, 1) lstm_wave(
    const __half* __restrict__ W,
    const float*  __restrict__ bsum,
    const __half* __restrict__ xh,
    __half* __restrict__ Hbuf,
    float* __restrict__ Cst,
    float* __restrict__ Hfin,
    int w)
{
    const int role = blockIdx.x >> 6;
    const int mblk = blockIdx.x & 63;
    if (role == 0 && w >= Tt) return;
    if (role == 1 && w == 0)  return;

    const int tt = role ? (w - 1) : w;
    const int p  = tt & 1;

    const __half *xs, *hs;
    __half *o_h;
    const __half* Wl;
    const float* bs;
    float* Cl;
    if (role == 0) {
        xs  = xh + (size_t)tt * BH;
        hs  = Hbuf + (size_t)p * BH;
        o_h = Hbuf + (size_t)(p ^ 1) * BH;
        Wl = W; bs = bsum; Cl = Cst;
    } else {
        xs  = Hbuf + (size_t)(p ^ 1) * BH;      // layer0 fresh hidden @ tt
        hs  = Hbuf + (size_t)(2 + p) * BH;
        o_h = Hbuf + (size_t)(2 + (p ^ 1)) * BH;
        Wl = W + WPL; bs = bsum + M4H; Cl = Cst + BH;
    }

    extern __shared__ char smem[];
    const int tid  = threadIdx.x;
    const int grp  = tid >> 8;           // K-split group: 0 -> x half, 1 -> h half
    const int gtid = tid & 255;
    const int gwid = gtid >> 5, lane = tid & 31;
    const int sub  = gwid >> 1;          // k16 index within each k64 sub-chunk
    const int half = gwid & 1;           // N32 half
    const uint32_t sb = smem_u32(smem) + grp * GSZ;

    // fragment addressing (swizzled smem, 128B rows, per 8KB sub-tile)
    const int rA  = lane & 15;
    const int rB  = (lane & 7) + ((lane >> 4) << 3);
    const uint32_t qa = 2 * sub + (lane >> 4);
    const uint32_t qb = 2 * sub + ((lane >> 3) & 1);
    const uint32_t aOff = rA * 128 + (((qa ^ (rA & 7))) << 4);
    const uint32_t bOff = rB * 128 + (((qb ^ (rB & 7))) << 4);

    const __half* a_src = grp ? hs : xs;
    const __half* Wbase = Wl + (size_t)(mblk * 64) * KK + grp * 1024;

    // M64xN32 accumulators: acc[mt*4 + n8]
    float acc[16][4];
#pragma unroll
    for (int i = 0; i < 16; i++)
#pragma unroll
        for (int r = 0; r < 4; r++) acc[i][r] = 0.f;

    // K128 chunk: two k64 sub-tiles. A subs at stA+{0,8192}, B at stB+{0,8192}.
    auto load_chunk = [&](int lc) {
        const int st = lc % 3;
        const uint32_t stA = sb + st * STAGE;
        const uint32_t stB = stA + 16384;
        const int koff = lc * 128;
        // A: [2 sub][64 rows][8 q] = 1024 16B units; 4/thread
#pragma unroll
        for (int i = 0; i < 4; i++) {
            int u = gtid + i * 256;
            int s2 = u >> 9, rem = u & 511, row = rem >> 3, q = rem & 7;
            const __half* s = Wbase + (size_t)row * KK + koff + s2 * 64 + q * 8;
            cp16(stA + s2 * 8192 + row * 128 + ((q ^ (row & 7)) << 4), s);
        }
        // B: [2 sub][64 rows][8 q] = 1024 units; 4/thread
#pragma unroll
        for (int i = 0; i < 4; i++) {
            int u = gtid + i * 256;
            int s2 = u >> 9, rem = u & 511, row = rem >> 3, q = rem & 7;
            const __half* s = a_src + (size_t)row * Hh + koff + s2 * 64 + q * 8;
            cp16(stB + s2 * 8192 + row * 128 + ((q ^ (row & 7)) << 4), s);
        }
        CP_COMMIT();
    };

    load_chunk(0);
    load_chunk(1);

    for (int lc = 0; lc < 8; ++lc) {
        if (lc <= 6) CP_WAIT1();
        else         CP_WAIT0();
        gbar(grp);
        if (lc + 2 < 8) load_chunk(lc + 2);

        const uint32_t stA = sb + (lc % 3) * STAGE;
        const uint32_t stB = stA + 16384;
        const uint32_t bO  = stB + half * 4096 + bOff;   // rows half*32 + rB

        // all 12 LDSM first: sub-chunk 1 loads overlap sub-chunk 0 HMMAs
        uint32_t a0[4], a1[4], a2[4], a3[4], b0[4], b1[4];
        uint32_t c0[4], c1[4], c2[4], c3[4], d0[4], d1[4];
        LDSM4(a0, stA + aOff);
        LDSM4(a1, stA + aOff + 2048);
        LDSM4(a2, stA + aOff + 4096);
        LDSM4(a3, stA + aOff + 6144);
        LDSM4(b0, bO);
        LDSM4(b1, bO + 2048);
        LDSM4(c0, stA + 8192 + aOff);
        LDSM4(c1, stA + 8192 + aOff + 2048);
        LDSM4(c2, stA + 8192 + aOff + 4096);
        LDSM4(c3, stA + 8192 + aOff + 6144);
        LDSM4(d0, bO + 8192);
        LDSM4(d1, bO + 8192 + 2048);

        HMMA_BLOCK(a0, a1, a2, a3, b0, b1);     // sub-chunk 0
        HMMA_BLOCK(c0, c1, c2, c3, d0, d1);     // sub-chunk 1
    }

    // ---------------- epilogue: 8 partials -> fused LSTM cell -------------
    __syncthreads();                      // all stages consumed; overlay gb
    float* gb = (float*)smem;             // [8 partial][64 m][66] = 135168 B
    {
        float* myb = gb + (grp * 4 + sub) * (64 * 66);
        const int mrow = lane >> 2;
        const int ncol = 2 * (lane & 3);
#pragma unroll
        for (int i = 0; i < 16; i++) {
            const int mt = i >> 2, n8 = i & 3;
            const int m = mt * 16 + mrow;
            const int n = half * 32 + n8 * 8 + ncol;
            *(float2*)&myb[m * 66 + n]       = make_float2(acc[i][0], acc[i][1]);
            *(float2*)&myb[(m + 8) * 66 + n] = make_float2(acc[i][2], acc[i][3]);
        }
    }
    __syncthreads();

    // 512 threads x 2 cells: CTA covers 16 j (two 32-row perm blocks) x 64 b
#pragma unroll
    for (int k = 0; k < 2; k++) {
        const int c   = tid + k * 512;    // 0..1023
        const int b   = c >> 4;
        const int jl2 = c & 15;
        const int rowbase = (jl2 < 8) ? 0 : 32;
        const int jj  = jl2 & 7;
        const int j   = mblk * 16 + jl2;
        float gsum[4];
#pragma unroll
        for (int g = 0; g < 4; g++) {
            const int m = rowbase + g * 8 + jj;
            float s = 0.f;
#pragma unroll
            for (int pp = 0; pp < 8; pp++)
                s += gb[(pp * 64 + m) * 66 + b];
            gsum[g] = s;
        }
        float gi = gsum[0] + bs[j];
        float gf = gsum[1] + bs[1024 + j];
        float gg = gsum[2] + bs[2048 + j];
        float go = gsum[3] + bs[3072 + j];
        float cn = sigm(gf) * Cl[b * Hh + j] + sigm(gi) * tanh_(gg);
        Cl[b * Hh + j] = cn;
        float hn = sigm(go) * tanh_(cn);
        o_h[b * Hh + j] = __float2half(hn);
        if (role == 1 && tt == Tt - 1) Hfin[b * Hh + j] = hn;
    }
}

// ---------------- host launcher ----------------
extern "C" void kernel_launch(void* const* d_in, const int* in_sizes, int n_in,
                              void* d_out, int out_size) {
    const float* x_seq = (const float*)d_in[0];
    const float* h0    = (const float*)d_in[1];
    const float* c0    = (const float*)d_in[2];
    const float* Wih   = (const float*)d_in[3];
    const float* Whh   = (const float*)d_in[4];
    const float* bih   = (const float*)d_in[5];
    const float* bhh   = (const float*)d_in[6];

    cudaFuncSetAttribute(lstm_wave,
                         cudaFuncAttributeMaxDynamicSharedMemorySize, SMEM_TOTAL);

    void *p_xh, *p_w, *p_bs, *p_hh, *p_c, *p_hf;
    cudaGetSymbolAddress(&p_xh, g_xh);
    cudaGetSymbolAddress(&p_w,  g_W);
    cudaGetSymbolAddress(&p_bs, g_bsum);
    cudaGetSymbolAddress(&p_hh, g_Hh);
    cudaGetSymbolAddress(&p_c,  g_C);
    cudaGetSymbolAddress(&p_hf, g_Hf);

    split_x_kernel<<<8192, 256>>>(x_seq, Tt * BH);
    init_state_kernel<<<512, 256>>>(h0, c0, bih, bhh);
    prep_w_kernel<<<8192, 256>>>(Wih, Whh);

    for (int w = 0; w <= Tt; w++) {
        lstm_wave<<<128, 512, SMEM_TOTAL>>>(
            (const __half*)p_w, (const float*)p_bs,
            (const __half*)p_xh,
            (__half*)p_hh, (float*)p_c, (float*)p_hf, w);
    }
    cudaMemcpyAsync(d_out, p_hf, (size_t)BH * sizeof(float),
                    cudaMemcpyDeviceToDevice);
}

// round 15
// speedup vs baseline: 2.3056x; 1.0157x over previous
#include <cuda_runtime.h>
#include <cuda_fp16.h>
#include <cstdint>

// StackLSTM T=256, B=64, H=1024, L=2 — Round 15.
// R15 = R14 with the per-chunk LDSM burst INTERLEAVED into the HMMA stream:
// after the barrier only 3 LDSM issue (a0,b0,b1), HMMAs start immediately,
// and the remaining 9 LDSM are sliced between HMMA rows (asm volatile order
// is preserved by ptxas). Exposed crossbar head ~700 -> ~200 cyc per chunk.

#define Tt 256
#define Bb 64
#define Hh 1024
#define BH (Bb * Hh)                 // 65536
#define M4H 4096
#define KK 2048
#define WPL ((size_t)M4H * KK)       // fp16 elems per layer (single plane)
#define STAGE 32768                  // A 16KB (2 sub-tiles) + B 16KB
#define NSTAGE 3
#define GSZ (NSTAGE * STAGE)         // 98304 per group
#define SMEM_TOTAL (2 * GSZ)         // 196608 (epilogue 135168 overlays)

// ---------------- persistent device state ----------------
__device__ __half g_xh[Tt * BH];             // input seq, fp16
__device__ __half g_W[2 * WPL];              // [layer][4096 perm rows][2048]
__device__ float  g_bsum[2 * M4H];
__device__ __half g_Hh[2 * 2 * BH];          // [layer][parity][BH], fp16
__device__ float  g_C[2 * BH];
__device__ float  g_Hf[BH];                  // final top-layer hidden (fp32)

// ---------------- helpers ----------------
__device__ __forceinline__ uint32_t smem_u32(const void* p) {
    uint32_t a;
    asm("{ .reg .u64 t; cvta.to.shared.u64 t, %1; cvt.u32.u64 %0, t; }"
        : "=r"(a) : "l"(p));
    return a;
}
__device__ __forceinline__ void cp16(uint32_t d, const void* g) {
    asm volatile("cp.async.cg.shared.global [%0], [%1], 16;"
                 :: "r"(d), "l"(g) : "memory");
}
#define CP_COMMIT() asm volatile("cp.async.commit_group;" ::: "memory")
#define CP_WAIT1()  asm volatile("cp.async.wait_group 1;" ::: "memory")
#define CP_WAIT0()  asm volatile("cp.async.wait_group 0;" ::: "memory")

#define LDSM4(r, addr) \
    asm volatile("ldmatrix.sync.aligned.m8n8.x4.shared.b16 {%0,%1,%2,%3}, [%4];" \
        : "=r"((r)[0]), "=r"((r)[1]), "=r"((r)[2]), "=r"((r)[3]) : "r"(addr))

#define HMMA(d, a0, a1, a2, a3, b0, b1) \
    asm volatile("mma.sync.aligned.m16n8k16.row.col.f32.f16.f16.f32 " \
        "{%0,%1,%2,%3},{%4,%5,%6,%7},{%8,%9},{%0,%1,%2,%3};" \
        : "+f"((d)[0]), "+f"((d)[1]), "+f"((d)[2]), "+f"((d)[3]) \
        : "r"(a0), "r"(a1), "r"(a2), "r"(a3), "r"(b0), "r"(b1))

// 4 HMMA of one m16 row against the N32 frags fb0, fb1
#define HMMA_ROW(base, fa, fb0, fb1) do { \
    HMMA(acc[(base) + 0], fa[0],fa[1],fa[2],fa[3], fb0[0],fb0[1]); \
    HMMA(acc[(base) + 1], fa[0],fa[1],fa[2],fa[3], fb0[2],fb0[3]); \
    HMMA(acc[(base) + 2], fa[0],fa[1],fa[2],fa[3], fb1[0],fb1[1]); \
    HMMA(acc[(base) + 3], fa[0],fa[1],fa[2],fa[3], fb1[2],fb1[3]); \
} while (0)

__device__ __forceinline__ void gbar(int grp) {
    if (grp == 0) asm volatile("bar.sync 1, 256;" ::: "memory");
    else          asm volatile("bar.sync 2, 256;" ::: "memory");
}

__device__ __forceinline__ float sigm(float x) { return 1.0f / (1.0f + __expf(-x)); }
__device__ __forceinline__ float tanh_(float x) {
    float ax = fabsf(x);
    float e  = __expf(-2.0f * ax);
    return copysignf((1.0f - e) / (1.0f + e), x);
}

// ---------------- prep kernels ----------------
__global__ void split_x_kernel(const float* __restrict__ x, int n) {
    for (int i = blockIdx.x * blockDim.x + threadIdx.x; i < n;
         i += gridDim.x * blockDim.x)
        g_xh[i] = __float2half(x[i]);
}

__global__ void init_state_kernel(const float* __restrict__ h0,
                                  const float* __restrict__ c0,
                                  const float* __restrict__ bih,
                                  const float* __restrict__ bhh) {
    int t0 = blockIdx.x * blockDim.x + threadIdx.x;
    for (int idx = t0; idx < 2 * BH; idx += gridDim.x * blockDim.x) {
        int l = idx / BH, r = idx % BH;
        g_Hh[(l * 2 + 0) * BH + r] = __float2half(h0[idx]);
        g_C[idx] = c0[idx];
    }
    for (int idx = t0; idx < 2 * M4H; idx += gridDim.x * blockDim.x)
        g_bsum[idx] = bih[idx] + bhh[idx];
}

// g_W[l][p][k]: permuted row p: blk=p>>5 (32-row perm block), lcl=p&31,
// gate=lcl>>3, jl=lcl&7, j=blk*8+jl, src row=gate*1024+j. k<1024->Wih else Whh.
__global__ void prep_w_kernel(const float* __restrict__ Wih,
                              const float* __restrict__ Whh) {
    const long long per = (long long)M4H * KK;
    const long long n   = 2 * per;
    for (long long idx = blockIdx.x * (long long)blockDim.x + threadIdx.x; idx < n;
         idx += (long long)gridDim.x * blockDim.x) {
        int  l  = (int)(idx / per);
        long long r2 = idx % per;
        int  p  = (int)(r2 / KK), k = (int)(r2 % KK);
        int  blk = p >> 5, lcl = p & 31;
        int  gate = lcl >> 3, jl = lcl & 7;
        int  j = blk * 8 + jl;
        int  srow = gate * 1024 + j;
        float w = (k < 1024)
                ? Wih[(size_t)l * M4H * Hh + (size_t)srow * Hh + k]
                : Whh[(size_t)l * M4H * Hh + (size_t)srow * Hh + (k - 1024)];
        g_W[idx] = __float2half(w);
    }
}

// ---------------- wave kernel: layer0[w] || layer1[w-1] ----------------
// grid = 128: blocks 0..63 role 0 (layer0, M64 tile mblk), 64..127 role 1.
// block = 512 = 2 K-split groups x 8 warps; warp: sub = k16 slot, half = N32.
// Warp tile M64 x N32; per K128 chunk: 12 LDSM.x4 interleaved with 32 HMMA.
__global__ void __launch_bounds__(512, 1) lstm_wave(
    const __half* __restrict__ W,
    const float*  __restrict__ bsum,
    const __half* __restrict__ xh,
    __half* __restrict__ Hbuf,
    float* __restrict__ Cst,
    float* __restrict__ Hfin,
    int w)
{
    const int role = blockIdx.x >> 6;
    const int mblk = blockIdx.x & 63;
    if (role == 0 && w >= Tt) return;
    if (role == 1 && w == 0)  return;

    const int tt = role ? (w - 1) : w;
    const int p  = tt & 1;

    const __half *xs, *hs;
    __half *o_h;
    const __half* Wl;
    const float* bs;
    float* Cl;
    if (role == 0) {
        xs  = xh + (size_t)tt * BH;
        hs  = Hbuf + (size_t)p * BH;
        o_h = Hbuf + (size_t)(p ^ 1) * BH;
        Wl = W; bs = bsum; Cl = Cst;
    } else {
        xs  = Hbuf + (size_t)(p ^ 1) * BH;      // layer0 fresh hidden @ tt
        hs  = Hbuf + (size_t)(2 + p) * BH;
        o_h = Hbuf + (size_t)(2 + (p ^ 1)) * BH;
        Wl = W + WPL; bs = bsum + M4H; Cl = Cst + BH;
    }

    extern __shared__ char smem[];
    const int tid  = threadIdx.x;
    const int grp  = tid >> 8;           // K-split group: 0 -> x half, 1 -> h half
    const int gtid = tid & 255;
    const int gwid = gtid >> 5, lane = tid & 31;
    const int sub  = gwid >> 1;          // k16 index within each k64 sub-chunk
    const int half = gwid & 1;           // N32 half
    const uint32_t sb = smem_u32(smem) + grp * GSZ;

    // fragment addressing (swizzled smem, 128B rows, per 8KB sub-tile)
    const int rA  = lane & 15;
    const int rB  = (lane & 7) + ((lane >> 4) << 3);
    const uint32_t qa = 2 * sub + (lane >> 4);
    const uint32_t qb = 2 * sub + ((lane >> 3) & 1);
    const uint32_t aOff = rA * 128 + (((qa ^ (rA & 7))) << 4);
    const uint32_t bOff = rB * 128 + (((qb ^ (rB & 7))) << 4);

    const __half* a_src = grp ? hs : xs;
    const __half* Wbase = Wl + (size_t)(mblk * 64) * KK + grp * 1024;

    // M64xN32 accumulators: acc[mt*4 + n8]
    float acc[16][4];
#pragma unroll
    for (int i = 0; i < 16; i++)
#pragma unroll
        for (int r = 0; r < 4; r++) acc[i][r] = 0.f;

    // K128 chunk: two k64 sub-tiles. A subs at stA+{0,8192}, B at stB+{0,8192}.
    auto load_chunk = [&](int lc) {
        const int st = lc % 3;
        const uint32_t stA = sb + st * STAGE;
        const uint32_t stB = stA + 16384;
        const int koff = lc * 128;
        // A: [2 sub][64 rows][8 q] = 1024 16B units; 4/thread
#pragma unroll
        for (int i = 0; i < 4; i++) {
            int u = gtid + i * 256;
            int s2 = u >> 9, rem = u & 511, row = rem >> 3, q = rem & 7;
            const __half* s = Wbase + (size_t)row * KK + koff + s2 * 64 + q * 8;
            cp16(stA + s2 * 8192 + row * 128 + ((q ^ (row & 7)) << 4), s);
        }
        // B: [2 sub][64 rows][8 q] = 1024 units; 4/thread
#pragma unroll
        for (int i = 0; i < 4; i++) {
            int u = gtid + i * 256;
            int s2 = u >> 9, rem = u & 511, row = rem >> 3, q = rem & 7;
            const __half* s = a_src + (size_t)row * Hh + koff + s2 * 64 + q * 8;
            cp16(stB + s2 * 8192 + row * 128 + ((q ^ (row & 7)) << 4), s);
        }
        CP_COMMIT();
    };

    load_chunk(0);
    load_chunk(1);

    for (int lc = 0; lc < 8; ++lc) {
        if (lc <= 6) CP_WAIT1();
        else         CP_WAIT0();
        gbar(grp);

        const uint32_t stA = sb + (lc % 3) * STAGE;
        const uint32_t stB = stA + 16384;
        const uint32_t bO  = stB + half * 4096 + bOff;   // rows half*32 + rB

        uint32_t a0[4], a1[4], a2[4], a3[4], b0[4], b1[4];
        uint32_t c0[4], c1[4], c2[4], c3[4], d0[4], d1[4];

        // minimal head: only what HMMA row 0 needs
        LDSM4(a0, stA + aOff);
        LDSM4(b0, bO);
        LDSM4(b1, bO + 2048);
        if (lc + 2 < 8) load_chunk(lc + 2);   // cp.async issues under LDSM lat

        HMMA_ROW(0, a0, b0, b1);              // starts as soon as frags land
        LDSM4(a1, stA + aOff + 2048);         // hide under row-0 HMMAs
        LDSM4(a2, stA + aOff + 4096);
        LDSM4(a3, stA + aOff + 6144);
        HMMA_ROW(4,  a1, b0, b1);
        HMMA_ROW(8,  a2, b0, b1);
        HMMA_ROW(12, a3, b0, b1);

        // sub-chunk 1: same pattern, LDSM hidden under sub-chunk-0 tail
        LDSM4(c0, stA + 8192 + aOff);
        LDSM4(d0, bO + 8192);
        LDSM4(d1, bO + 8192 + 2048);
        HMMA_ROW(0, c0, d0, d1);
        LDSM4(c1, stA + 8192 + aOff + 2048);
        LDSM4(c2, stA + 8192 + aOff + 4096);
        LDSM4(c3, stA + 8192 + aOff + 6144);
        HMMA_ROW(4,  c1, d0, d1);
        HMMA_ROW(8,  c2, d0, d1);
        HMMA_ROW(12, c3, d0, d1);
    }

    // ---------------- epilogue: 8 partials -> fused LSTM cell -------------
    __syncthreads();                      // all stages consumed; overlay gb
    float* gb = (float*)smem;             // [8 partial][64 m][66] = 135168 B
    {
        float* myb = gb + (grp * 4 + sub) * (64 * 66);
        const int mrow = lane >> 2;
        const int ncol = 2 * (lane & 3);
#pragma unroll
        for (int i = 0; i < 16; i++) {
            const int mt = i >> 2, n8 = i & 3;
            const int m = mt * 16 + mrow;
            const int n = half * 32 + n8 * 8 + ncol;
            *(float2*)&myb[m * 66 + n]       = make_float2(acc[i][0], acc[i][1]);
            *(float2*)&myb[(m + 8) * 66 + n] = make_float2(acc[i][2], acc[i][3]);
        }
    }
    __syncthreads();

    // 512 threads x 2 cells: CTA covers 16 j (two 32-row perm blocks) x 64 b
#pragma unroll
    for (int k = 0; k < 2; k++) {
        const int c   = tid + k * 512;    // 0..1023
        const int b   = c >> 4;
        const int jl2 = c & 15;
        const int rowbase = (jl2 < 8) ? 0 : 32;
        const int jj  = jl2 & 7;
        const int j   = mblk * 16 + jl2;
        float gsum[4];
#pragma unroll
        for (int g = 0; g < 4; g++) {
            const int m = rowbase + g * 8 + jj;
            float s = 0.f;
#pragma unroll
            for (int pp = 0; pp < 8; pp++)
                s += gb[(pp * 64 + m) * 66 + b];
            gsum[g] = s;
        }
        float gi = gsum[0] + bs[j];
        float gf = gsum[1] + bs[1024 + j];
        float gg = gsum[2] + bs[2048 + j];
        float go = gsum[3] + bs[3072 + j];
        float cn = sigm(gf) * Cl[b * Hh + j] + sigm(gi) * tanh_(gg);
        Cl[b * Hh + j] = cn;
        float hn = sigm(go) * tanh_(cn);
        o_h[b * Hh + j] = __float2half(hn);
        if (role == 1 && tt == Tt - 1) Hfin[b * Hh + j] = hn;
    }
}

// ---------------- host launcher ----------------
extern "C" void kernel_launch(void* const* d_in, const int* in_sizes, int n_in,
                              void* d_out, int out_size) {
    const float* x_seq = (const float*)d_in[0];
    const float* h0    = (const float*)d_in[1];
    const float* c0    = (const float*)d_in[2];
    const float* Wih   = (const float*)d_in[3];
    const float* Whh   = (const float*)d_in[4];
    const float* bih   = (const float*)d_in[5];
    const float* bhh   = (const float*)d_in[6];

    cudaFuncSetAttribute(lstm_wave,
                         cudaFuncAttributeMaxDynamicSharedMemorySize, SMEM_TOTAL);

    void *p_xh, *p_w, *p_bs, *p_hh, *p_c, *p_hf;
    cudaGetSymbolAddress(&p_xh, g_xh);
    cudaGetSymbolAddress(&p_w,  g_W);
    cudaGetSymbolAddress(&p_bs, g_bsum);
    cudaGetSymbolAddress(&p_hh, g_Hh);
    cudaGetSymbolAddress(&p_c,  g_C);
    cudaGetSymbolAddress(&p_hf, g_Hf);

    split_x_kernel<<<8192, 256>>>(x_seq, Tt * BH);
    init_state_kernel<<<512, 256>>>(h0, c0, bih, bhh);
    prep_w_kernel<<<8192, 256>>>(Wih, Whh);

    for (int w = 0; w <= Tt; w++) {
        lstm_wave<<<128, 512, SMEM_TOTAL>>>(
            (const __half*)p_w, (const float*)p_bs,
            (const __half*)p_xh,
            (__half*)p_hh, (float*)p_c, (float*)p_hf, w);
    }
    cudaMemcpyAsync(d_out, p_hf, (size_t)BH * sizeof(float),
                    cudaMemcpyDeviceToDevice);
}

// round 16
// speedup vs baseline: 2.5035x; 1.0858x over previous
#include <cuda_runtime.h>
#include <cuda_fp16.h>
#include <cstdint>

// StackLSTM T=256, B=64, H=1024, L=2 — Round 16.
// R16: break SM-level phase lock (LDSM-phase vs HMMA-phase convoy caused by
// the per-chunk group barrier at 1 CTA/SM) with 2 CO-RESIDENT CTAs per SM:
// 256-thread CTAs, M32 tile, grid 256 (2 roles x 128 mblk), 96KB smem/CTA,
// __launch_bounds__(256,2). Per-SM work identical; phases decorrelate and
// occupancy doubles. fp16 single-plane weights, wave fusion kept.

#define Tt 256
#define Bb 64
#define Hh 1024
#define BH (Bb * Hh)                 // 65536
#define M4H 4096
#define KK 2048
#define WPL ((size_t)M4H * KK)       // fp16 elems per layer (single plane)
#define STAGE 12288                  // A 4KB + B 8KB  (K64 chunk, M32 tile)
#define NSTAGE 4
#define GSZ (NSTAGE * STAGE)         // 49152 per group
#define SMEM_TOTAL (2 * GSZ)         // 98304 (epilogue 33792 overlays)

// ---------------- persistent device state ----------------
__device__ __half g_xh[Tt * BH];             // input seq, fp16
__device__ __half g_W[2 * WPL];              // [layer][4096 perm rows][2048]
__device__ float  g_bsum[2 * M4H];
__device__ __half g_Hh[2 * 2 * BH];          // [layer][parity][BH], fp16
__device__ float  g_C[2 * BH];
__device__ float  g_Hf[BH];                  // final top-layer hidden (fp32)

// ---------------- helpers ----------------
__device__ __forceinline__ uint32_t smem_u32(const void* p) {
    uint32_t a;
    asm("{ .reg .u64 t; cvta.to.shared.u64 t, %1; cvt.u32.u64 %0, t; }"
        : "=r"(a) : "l"(p));
    return a;
}
__device__ __forceinline__ void cp16(uint32_t d, const void* g) {
    asm volatile("cp.async.cg.shared.global [%0], [%1], 16;"
                 :: "r"(d), "l"(g) : "memory");
}
#define CP_COMMIT() asm volatile("cp.async.commit_group;" ::: "memory")
#define CP_WAIT2()  asm volatile("cp.async.wait_group 2;" ::: "memory")
#define CP_WAIT1()  asm volatile("cp.async.wait_group 1;" ::: "memory")
#define CP_WAIT0()  asm volatile("cp.async.wait_group 0;" ::: "memory")

#define LDSM4(r, addr) \
    asm volatile("ldmatrix.sync.aligned.m8n8.x4.shared.b16 {%0,%1,%2,%3}, [%4];" \
        : "=r"((r)[0]), "=r"((r)[1]), "=r"((r)[2]), "=r"((r)[3]) : "r"(addr))

#define HMMA(d, a0, a1, a2, a3, b0, b1) \
    asm volatile("mma.sync.aligned.m16n8k16.row.col.f32.f16.f16.f32 " \
        "{%0,%1,%2,%3},{%4,%5,%6,%7},{%8,%9},{%0,%1,%2,%3};" \
        : "+f"((d)[0]), "+f"((d)[1]), "+f"((d)[2]), "+f"((d)[3]) \
        : "r"(a0), "r"(a1), "r"(a2), "r"(a3), "r"(b0), "r"(b1))

__device__ __forceinline__ void gbar(int grp) {
    if (grp == 0) asm volatile("bar.sync 1, 128;" ::: "memory");
    else          asm volatile("bar.sync 2, 128;" ::: "memory");
}

__device__ __forceinline__ float sigm(float x) { return 1.0f / (1.0f + __expf(-x)); }
__device__ __forceinline__ float tanh_(float x) {
    float ax = fabsf(x);
    float e  = __expf(-2.0f * ax);
    return copysignf((1.0f - e) / (1.0f + e), x);
}

// ---------------- prep kernels ----------------
__global__ void split_x_kernel(const float* __restrict__ x, int n) {
    for (int i = blockIdx.x * blockDim.x + threadIdx.x; i < n;
         i += gridDim.x * blockDim.x)
        g_xh[i] = __float2half(x[i]);
}

__global__ void init_state_kernel(const float* __restrict__ h0,
                                  const float* __restrict__ c0,
                                  const float* __restrict__ bih,
                                  const float* __restrict__ bhh) {
    int t0 = blockIdx.x * blockDim.x + threadIdx.x;
    for (int idx = t0; idx < 2 * BH; idx += gridDim.x * blockDim.x) {
        int l = idx / BH, r = idx % BH;
        g_Hh[(l * 2 + 0) * BH + r] = __float2half(h0[idx]);
        g_C[idx] = c0[idx];
    }
    for (int idx = t0; idx < 2 * M4H; idx += gridDim.x * blockDim.x)
        g_bsum[idx] = bih[idx] + bhh[idx];
}

// g_W[l][p][k]: permuted row p: blk=p>>5 (32-row perm block), lcl=p&31,
// gate=lcl>>3, jl=lcl&7, j=blk*8+jl, src row=gate*1024+j. k<1024->Wih else Whh.
__global__ void prep_w_kernel(const float* __restrict__ Wih,
                              const float* __restrict__ Whh) {
    const long long per = (long long)M4H * KK;
    const long long n   = 2 * per;
    for (long long idx = blockIdx.x * (long long)blockDim.x + threadIdx.x; idx < n;
         idx += (long long)gridDim.x * blockDim.x) {
        int  l  = (int)(idx / per);
        long long r2 = idx % per;
        int  p  = (int)(r2 / KK), k = (int)(r2 % KK);
        int  blk = p >> 5, lcl = p & 31;
        int  gate = lcl >> 3, jl = lcl & 7;
        int  j = blk * 8 + jl;
        int  srow = gate * 1024 + j;
        float w = (k < 1024)
                ? Wih[(size_t)l * M4H * Hh + (size_t)srow * Hh + k]
                : Whh[(size_t)l * M4H * Hh + (size_t)srow * Hh + (k - 1024)];
        g_W[idx] = __float2half(w);
    }
}

// ---------------- wave kernel: layer0[w] || layer1[w-1] ----------------
// grid = 256: blocks 0..127 role 0 (layer0, M32 tile mblk), 128..255 role 1.
// block = 256 = 2 K-split groups x 4 warps; warp: sub = k32 slot, half = N32.
// Warp tile M32 x N32; K64 chunks, 16 iterations, 4-stage cp.async pipeline.
__global__ void __launch_bounds__(256, 2) lstm_wave(
    const __half* __restrict__ W,
    const float*  __restrict__ bsum,
    const __half* __restrict__ xh,
    __half* __restrict__ Hbuf,
    float* __restrict__ Cst,
    float* __restrict__ Hfin,
    int w)
{
    const int role = blockIdx.x >> 7;
    const int mblk = blockIdx.x & 127;
    if (role == 0 && w >= Tt) return;
    if (role == 1 && w == 0)  return;

    const int tt = role ? (w - 1) : w;
    const int p  = tt & 1;

    const __half *xs, *hs;
    __half *o_h;
    const __half* Wl;
    const float* bs;
    float* Cl;
    if (role == 0) {
        xs  = xh + (size_t)tt * BH;
        hs  = Hbuf + (size_t)p * BH;
        o_h = Hbuf + (size_t)(p ^ 1) * BH;
        Wl = W; bs = bsum; Cl = Cst;
    } else {
        xs  = Hbuf + (size_t)(p ^ 1) * BH;      // layer0 fresh hidden @ tt
        hs  = Hbuf + (size_t)(2 + p) * BH;
        o_h = Hbuf + (size_t)(2 + (p ^ 1)) * BH;
        Wl = W + WPL; bs = bsum + M4H; Cl = Cst + BH;
    }

    extern __shared__ char smem[];
    const int tid  = threadIdx.x;
    const int grp  = tid >> 7;           // K-split group: 0 -> x half, 1 -> h half
    const int gtid = tid & 127;
    const int gwid = gtid >> 5, lane = tid & 31;
    const int sub  = gwid >> 1;          // k32 slot within K64 chunk (0..1)
    const int half = gwid & 1;           // N32 half
    const uint32_t sb = smem_u32(smem) + grp * GSZ;

    // fragment addressing (swizzled smem, 128B rows)
    const int rA  = lane & 15;
    const int rB  = (lane & 7) + ((lane >> 4) << 3);
    // k16 slots handled by this warp: s0 = 2*sub, s1 = 2*sub+1
    const uint32_t qa0 = 4 * sub     + (lane >> 4);
    const uint32_t qa1 = 4 * sub + 2 + (lane >> 4);
    const uint32_t qb0 = 4 * sub     + ((lane >> 3) & 1);
    const uint32_t qb1 = 4 * sub + 2 + ((lane >> 3) & 1);
    const uint32_t aOff0 = rA * 128 + ((qa0 ^ (rA & 7)) << 4);
    const uint32_t aOff1 = rA * 128 + ((qa1 ^ (rA & 7)) << 4);
    const uint32_t bRow  = (half * 32 + rB) * 128;
    const uint32_t bOff0 = bRow + ((qb0 ^ ((half * 32 + rB) & 7)) << 4);
    const uint32_t bOff1 = bRow + ((qb1 ^ ((half * 32 + rB) & 7)) << 4);

    const __half* a_src = grp ? hs : xs;
    const __half* Wbase = Wl + (size_t)(mblk * 32) * KK + grp * 1024;

    // M32xN32 accumulators: acc[mt*4 + n8]
    float acc[8][4];
#pragma unroll
    for (int i = 0; i < 8; i++)
#pragma unroll
        for (int r = 0; r < 4; r++) acc[i][r] = 0.f;

    // K64 chunk: A [32 rows][128B] at +0 (4KB), B [64 rows][128B] at +4096.
    auto load_chunk = [&](int lc) {
        const int st = lc & 3;
        const uint32_t stA = sb + st * STAGE;
        const uint32_t stB = stA + 4096;
        const int koff = lc * 64;
        // A: [32 rows][8 q] = 256 16B units; 2/thread (128 thr)
#pragma unroll
        for (int i = 0; i < 2; i++) {
            int u = gtid + i * 128;
            int row = u >> 3, q = u & 7;
            const __half* s = Wbase + (size_t)row * KK + koff + q * 8;
            cp16(stA + row * 128 + ((q ^ (row & 7)) << 4), s);
        }
        // B: [64 rows][8 q] = 512 units; 4/thread
#pragma unroll
        for (int i = 0; i < 4; i++) {
            int u = gtid + i * 128;
            int row = u >> 3, q = u & 7;
            const __half* s = a_src + (size_t)row * Hh + koff + q * 8;
            cp16(stB + row * 128 + ((q ^ (row & 7)) << 4), s);
        }
        CP_COMMIT();
    };

    load_chunk(0);
    load_chunk(1);
    load_chunk(2);

    for (int lc = 0; lc < 16; ++lc) {
        if (lc <= 13)      CP_WAIT2();
        else if (lc == 14) CP_WAIT1();
        else               CP_WAIT0();
        gbar(grp);
        if (lc + 3 < 16) load_chunk(lc + 3);

        const uint32_t stA = sb + (lc & 3) * STAGE;
        const uint32_t stB = stA + 4096;

        uint32_t a0[4], a1[4], b0[4], b1[4];
        // k16 slot s0
        LDSM4(a0, stA + aOff0);               // m16 tiles 0,1 packed in x4
        LDSM4(a1, stA + aOff0 + 2048);
        LDSM4(b0, stB + bOff0);               // n16 tiles 0,1 of this half
        LDSM4(b1, stB + bOff0 + 2048);
        HMMA(acc[0], a0[0],a0[1],a0[2],a0[3], b0[0],b0[1]);
        HMMA(acc[1], a0[0],a0[1],a0[2],a0[3], b0[2],b0[3]);
        HMMA(acc[2], a0[0],a0[1],a0[2],a0[3], b1[0],b1[1]);
        HMMA(acc[3], a0[0],a0[1],a0[2],a0[3], b1[2],b1[3]);
        HMMA(acc[4], a1[0],a1[1],a1[2],a1[3], b0[0],b0[1]);
        HMMA(acc[5], a1[0],a1[1],a1[2],a1[3], b0[2],b0[3]);
        HMMA(acc[6], a1[0],a1[1],a1[2],a1[3], b1[0],b1[1]);
        HMMA(acc[7], a1[0],a1[1],a1[2],a1[3], b1[2],b1[3]);
        // k16 slot s1
        LDSM4(a0, stA + aOff1);
        LDSM4(a1, stA + aOff1 + 2048);
        LDSM4(b0, stB + bOff1);
        LDSM4(b1, stB + bOff1 + 2048);
        HMMA(acc[0], a0[0],a0[1],a0[2],a0[3], b0[0],b0[1]);
        HMMA(acc[1], a0[0],a0[1],a0[2],a0[3], b0[2],b0[3]);
        HMMA(acc[2], a0[0],a0[1],a0[2],a0[3], b1[0],b1[1]);
        HMMA(acc[3], a0[0],a0[1],a0[2],a0[3], b1[2],b1[3]);
        HMMA(acc[4], a1[0],a1[1],a1[2],a1[3], b0[0],b0[1]);
        HMMA(acc[5], a1[0],a1[1],a1[2],a1[3], b0[2],b0[3]);
        HMMA(acc[6], a1[0],a1[1],a1[2],a1[3], b1[0],b1[1]);
        HMMA(acc[7], a1[0],a1[1],a1[2],a1[3], b1[2],b1[3]);
    }

    // ---------------- epilogue: 4 partials -> fused LSTM cell -------------
    __syncthreads();                      // all stages consumed; overlay gb
    float* gb = (float*)smem;             // [4 partial][32 m][66] = 33792 B
    {
        float* myb = gb + (grp * 2 + sub) * (32 * 66);
        const int mrow = lane >> 2;
        const int ncol = 2 * (lane & 3);
#pragma unroll
        for (int i = 0; i < 8; i++) {
            const int mt = i >> 2, n8 = i & 3;
            const int m = mt * 16 + mrow;
            const int n = half * 32 + n8 * 8 + ncol;
            *(float2*)&myb[m * 66 + n]       = make_float2(acc[i][0], acc[i][1]);
            *(float2*)&myb[(m + 8) * 66 + n] = make_float2(acc[i][2], acc[i][3]);
        }
    }
    __syncthreads();

    // 256 threads x 2 cells: CTA covers 8 j x 64 b
#pragma unroll
    for (int k = 0; k < 2; k++) {
        const int c  = tid + k * 256;     // 0..511
        const int b  = c >> 3;
        const int jl = c & 7;
        const int j  = mblk * 8 + jl;
        float gsum[4];
#pragma unroll
        for (int g = 0; g < 4; g++) {
            const int m = g * 8 + jl;
            float s = 0.f;
#pragma unroll
            for (int pp = 0; pp < 4; pp++)
                s += gb[(pp * 32 + m) * 66 + b];
            gsum[g] = s;
        }
        float gi = gsum[0] + bs[j];
        float gf = gsum[1] + bs[1024 + j];
        float gg = gsum[2] + bs[2048 + j];
        float go = gsum[3] + bs[3072 + j];
        float cn = sigm(gf) * Cl[b * Hh + j] + sigm(gi) * tanh_(gg);
        Cl[b * Hh + j] = cn;
        float hn = sigm(go) * tanh_(cn);
        o_h[b * Hh + j] = __float2half(hn);
        if (role == 1 && tt == Tt - 1) Hfin[b * Hh + j] = hn;
    }
}

// ---------------- host launcher ----------------
extern "C" void kernel_launch(void* const* d_in, const int* in_sizes, int n_in,
                              void* d_out, int out_size) {
    const float* x_seq = (const float*)d_in[0];
    const float* h0    = (const float*)d_in[1];
    const float* c0    = (const float*)d_in[2];
    const float* Wih   = (const float*)d_in[3];
    const float* Whh   = (const float*)d_in[4];
    const float* bih   = (const float*)d_in[5];
    const float* bhh   = (const float*)d_in[6];

    cudaFuncSetAttribute(lstm_wave,
                         cudaFuncAttributeMaxDynamicSharedMemorySize, SMEM_TOTAL);

    void *p_xh, *p_w, *p_bs, *p_hh, *p_c, *p_hf;
    cudaGetSymbolAddress(&p_xh, g_xh);
    cudaGetSymbolAddress(&p_w,  g_W);
    cudaGetSymbolAddress(&p_bs, g_bsum);
    cudaGetSymbolAddress(&p_hh, g_Hh);
    cudaGetSymbolAddress(&p_c,  g_C);
    cudaGetSymbolAddress(&p_hf, g_Hf);

    split_x_kernel<<<8192, 256>>>(x_seq, Tt * BH);
    init_state_kernel<<<512, 256>>>(h0, c0, bih, bhh);
    prep_w_kernel<<<8192, 256>>>(Wih, Whh);

    for (int w = 0; w <= Tt; w++) {
        lstm_wave<<<256, 256, SMEM_TOTAL>>>(
            (const __half*)p_w, (const float*)p_bs,
            (const __half*)p_xh,
            (__half*)p_hh, (float*)p_c, (float*)p_hf, w);
    }
    cudaMemcpyAsync(d_out, p_hf, (size_t)BH * sizeof(float),
                    cudaMemcpyDeviceToDevice);
}

// round 17
// speedup vs baseline: 2.6422x; 1.0554x over previous
#include <cuda_runtime.h>
#include <cuda_fp16.h>
#include <cstdint>

// StackLSTM T=256, B=64, H=1024, L=2 — Round 17.
// R17 = R16 (2 co-resident CTAs/SM, M32 tiles, fp16 single-plane, wave
// fusion) + PDL (programmatic dependent launch):
//  - wave kernels launched with programmaticStreamSerializationAllowed=1
//  - griddepcontrol.launch_dependents after the mainloop -> next wave's CTAs
//    launch during our epilogue
//  - weight (A) cp.asyncs for chunks 0..2 issue BEFORE griddepcontrol.wait
//    (weights are wave-invariant); only activation (B) loads wait.

#define Tt 256
#define Bb 64
#define Hh 1024
#define BH (Bb * Hh)                 // 65536
#define M4H 4096
#define KK 2048
#define WPL ((size_t)M4H * KK)       // fp16 elems per layer (single plane)
#define STAGE 12288                  // A 4KB + B 8KB  (K64 chunk, M32 tile)
#define NSTAGE 4
#define GSZ (NSTAGE * STAGE)         // 49152 per group
#define SMEM_TOTAL (2 * GSZ)         // 98304 (epilogue 33792 overlays)

// ---------------- persistent device state ----------------
__device__ __half g_xh[Tt * BH];             // input seq, fp16
__device__ __half g_W[2 * WPL];              // [layer][4096 perm rows][2048]
__device__ float  g_bsum[2 * M4H];
__device__ __half g_Hh[2 * 2 * BH];          // [layer][parity][BH], fp16
__device__ float  g_C[2 * BH];
__device__ float  g_Hf[BH];                  // final top-layer hidden (fp32)

// ---------------- helpers ----------------
__device__ __forceinline__ uint32_t smem_u32(const void* p) {
    uint32_t a;
    asm("{ .reg .u64 t; cvta.to.shared.u64 t, %1; cvt.u32.u64 %0, t; }"
        : "=r"(a) : "l"(p));
    return a;
}
__device__ __forceinline__ void cp16(uint32_t d, const void* g) {
    asm volatile("cp.async.cg.shared.global [%0], [%1], 16;"
                 :: "r"(d), "l"(g) : "memory");
}
#define CP_COMMIT() asm volatile("cp.async.commit_group;" ::: "memory")
#define CP_WAIT2()  asm volatile("cp.async.wait_group 2;" ::: "memory")
#define CP_WAIT1()  asm volatile("cp.async.wait_group 1;" ::: "memory")
#define CP_WAIT0()  asm volatile("cp.async.wait_group 0;" ::: "memory")

#define GRIDDEP_WAIT()   asm volatile("griddepcontrol.wait;" ::: "memory")
#define GRIDDEP_LAUNCH() asm volatile("griddepcontrol.launch_dependents;" ::: "memory")

#define LDSM4(r, addr) \
    asm volatile("ldmatrix.sync.aligned.m8n8.x4.shared.b16 {%0,%1,%2,%3}, [%4];" \
        : "=r"((r)[0]), "=r"((r)[1]), "=r"((r)[2]), "=r"((r)[3]) : "r"(addr))

#define HMMA(d, a0, a1, a2, a3, b0, b1) \
    asm volatile("mma.sync.aligned.m16n8k16.row.col.f32.f16.f16.f32 " \
        "{%0,%1,%2,%3},{%4,%5,%6,%7},{%8,%9},{%0,%1,%2,%3};" \
        : "+f"((d)[0]), "+f"((d)[1]), "+f"((d)[2]), "+f"((d)[3]) \
        : "r"(a0), "r"(a1), "r"(a2), "r"(a3), "r"(b0), "r"(b1))

__device__ __forceinline__ void gbar(int grp) {
    if (grp == 0) asm volatile("bar.sync 1, 128;" ::: "memory");
    else          asm volatile("bar.sync 2, 128;" ::: "memory");
}

__device__ __forceinline__ float sigm(float x) { return 1.0f / (1.0f + __expf(-x)); }
__device__ __forceinline__ float tanh_(float x) {
    float ax = fabsf(x);
    float e  = __expf(-2.0f * ax);
    return copysignf((1.0f - e) / (1.0f + e), x);
}

// ---------------- prep kernels ----------------
__global__ void split_x_kernel(const float* __restrict__ x, int n) {
    for (int i = blockIdx.x * blockDim.x + threadIdx.x; i < n;
         i += gridDim.x * blockDim.x)
        g_xh[i] = __float2half(x[i]);
}

__global__ void init_state_kernel(const float* __restrict__ h0,
                                  const float* __restrict__ c0,
                                  const float* __restrict__ bih,
                                  const float* __restrict__ bhh) {
    int t0 = blockIdx.x * blockDim.x + threadIdx.x;
    for (int idx = t0; idx < 2 * BH; idx += gridDim.x * blockDim.x) {
        int l = idx / BH, r = idx % BH;
        g_Hh[(l * 2 + 0) * BH + r] = __float2half(h0[idx]);
        g_C[idx] = c0[idx];
    }
    for (int idx = t0; idx < 2 * M4H; idx += gridDim.x * blockDim.x)
        g_bsum[idx] = bih[idx] + bhh[idx];
}

// g_W[l][p][k]: permuted row p: blk=p>>5 (32-row perm block), lcl=p&31,
// gate=lcl>>3, jl=lcl&7, j=blk*8+jl, src row=gate*1024+j. k<1024->Wih else Whh.
__global__ void prep_w_kernel(const float* __restrict__ Wih,
                              const float* __restrict__ Whh) {
    const long long per = (long long)M4H * KK;
    const long long n   = 2 * per;
    for (long long idx = blockIdx.x * (long long)blockDim.x + threadIdx.x; idx < n;
         idx += (long long)gridDim.x * blockDim.x) {
        int  l  = (int)(idx / per);
        long long r2 = idx % per;
        int  p  = (int)(r2 / KK), k = (int)(r2 % KK);
        int  blk = p >> 5, lcl = p & 31;
        int  gate = lcl >> 3, jl = lcl & 7;
        int  j = blk * 8 + jl;
        int  srow = gate * 1024 + j;
        float w = (k < 1024)
                ? Wih[(size_t)l * M4H * Hh + (size_t)srow * Hh + k]
                : Whh[(size_t)l * M4H * Hh + (size_t)srow * Hh + (k - 1024)];
        g_W[idx] = __float2half(w);
    }
}

// ---------------- wave kernel: layer0[w] || layer1[w-1] ----------------
// grid = 256: blocks 0..127 role 0 (layer0, M32 tile mblk), 128..255 role 1.
// block = 256 = 2 K-split groups x 4 warps; warp: sub = k32 slot, half = N32.
__global__ void __launch_bounds__(256, 2) lstm_wave(
    const __half* __restrict__ W,
    const float*  __restrict__ bsum,
    const __half* __restrict__ xh,
    __half* __restrict__ Hbuf,
    float* __restrict__ Cst,
    float* __restrict__ Hfin,
    int w)
{
    const int role = blockIdx.x >> 7;
    const int mblk = blockIdx.x & 127;
    if (role == 0 && w >= Tt) { GRIDDEP_WAIT(); return; }
    if (role == 1 && w == 0)  { GRIDDEP_WAIT(); return; }

    const int tt = role ? (w - 1) : w;
    const int p  = tt & 1;

    const __half *xs, *hs;
    __half *o_h;
    const __half* Wl;
    const float* bs;
    float* Cl;
    if (role == 0) {
        xs  = xh + (size_t)tt * BH;
        hs  = Hbuf + (size_t)p * BH;
        o_h = Hbuf + (size_t)(p ^ 1) * BH;
        Wl = W; bs = bsum; Cl = Cst;
    } else {
        xs  = Hbuf + (size_t)(p ^ 1) * BH;      // layer0 fresh hidden @ tt
        hs  = Hbuf + (size_t)(2 + p) * BH;
        o_h = Hbuf + (size_t)(2 + (p ^ 1)) * BH;
        Wl = W + WPL; bs = bsum + M4H; Cl = Cst + BH;
    }

    extern __shared__ char smem[];
    const int tid  = threadIdx.x;
    const int grp  = tid >> 7;           // K-split group: 0 -> x half, 1 -> h half
    const int gtid = tid & 127;
    const int gwid = gtid >> 5, lane = tid & 31;
    const int sub  = gwid >> 1;          // k32 slot within K64 chunk (0..1)
    const int half = gwid & 1;           // N32 half
    const uint32_t sb = smem_u32(smem) + grp * GSZ;

    // fragment addressing (swizzled smem, 128B rows)
    const int rA  = lane & 15;
    const int rB  = (lane & 7) + ((lane >> 4) << 3);
    const uint32_t qa0 = 4 * sub     + (lane >> 4);
    const uint32_t qa1 = 4 * sub + 2 + (lane >> 4);
    const uint32_t qb0 = 4 * sub     + ((lane >> 3) & 1);
    const uint32_t qb1 = 4 * sub + 2 + ((lane >> 3) & 1);
    const uint32_t aOff0 = rA * 128 + ((qa0 ^ (rA & 7)) << 4);
    const uint32_t aOff1 = rA * 128 + ((qa1 ^ (rA & 7)) << 4);
    const uint32_t bRow  = (half * 32 + rB) * 128;
    const uint32_t bOff0 = bRow + ((qb0 ^ ((half * 32 + rB) & 7)) << 4);
    const uint32_t bOff1 = bRow + ((qb1 ^ ((half * 32 + rB) & 7)) << 4);

    const __half* a_src = grp ? hs : xs;
    const __half* Wbase = Wl + (size_t)(mblk * 32) * KK + grp * 1024;

    // M32xN32 accumulators: acc[mt*4 + n8]
    float acc[8][4];
#pragma unroll
    for (int i = 0; i < 8; i++)
#pragma unroll
        for (int r = 0; r < 4; r++) acc[i][r] = 0.f;

    // A (weights): wave-independent, may issue BEFORE griddepcontrol.wait
    auto loadA = [&](int lc) {
        const int st = lc & 3;
        const uint32_t stA = sb + st * STAGE;
        const int koff = lc * 64;
#pragma unroll
        for (int i = 0; i < 2; i++) {
            int u = gtid + i * 128;
            int row = u >> 3, q = u & 7;
            const __half* s = Wbase + (size_t)row * KK + koff + q * 8;
            cp16(stA + row * 128 + ((q ^ (row & 7)) << 4), s);
        }
    };
    // B (activations): depends on previous wave's output
    auto loadB = [&](int lc) {
        const int st = lc & 3;
        const uint32_t stB = sb + st * STAGE + 4096;
        const int koff = lc * 64;
#pragma unroll
        for (int i = 0; i < 4; i++) {
            int u = gtid + i * 128;
            int row = u >> 3, q = u & 7;
            const __half* s = a_src + (size_t)row * Hh + koff + q * 8;
            cp16(stB + row * 128 + ((q ^ (row & 7)) << 4), s);
        }
    };

    // prologue: weight prefetch overlaps previous wave's tail (PDL early
    // launch), then wait for the previous wave, then activation loads.
    loadA(0); loadA(1); loadA(2);
    GRIDDEP_WAIT();
    loadB(0); CP_COMMIT();          // g0 = {A0,A1,A2,B0}
    loadB(1); CP_COMMIT();          // g1 = {B1}
    loadB(2); CP_COMMIT();          // g2 = {B2}

    for (int lc = 0; lc < 16; ++lc) {
        if (lc <= 13)      CP_WAIT2();
        else if (lc == 14) CP_WAIT1();
        else               CP_WAIT0();
        gbar(grp);
        if (lc + 3 < 16) { loadA(lc + 3); loadB(lc + 3); CP_COMMIT(); }

        const uint32_t stA = sb + (lc & 3) * STAGE;
        const uint32_t stB = stA + 4096;

        uint32_t a0[4], a1[4], b0[4], b1[4];
        // k16 slot s0
        LDSM4(a0, stA + aOff0);
        LDSM4(a1, stA + aOff0 + 2048);
        LDSM4(b0, stB + bOff0);
        LDSM4(b1, stB + bOff0 + 2048);
        HMMA(acc[0], a0[0],a0[1],a0[2],a0[3], b0[0],b0[1]);
        HMMA(acc[1], a0[0],a0[1],a0[2],a0[3], b0[2],b0[3]);
        HMMA(acc[2], a0[0],a0[1],a0[2],a0[3], b1[0],b1[1]);
        HMMA(acc[3], a0[0],a0[1],a0[2],a0[3], b1[2],b1[3]);
        HMMA(acc[4], a1[0],a1[1],a1[2],a1[3], b0[0],b0[1]);
        HMMA(acc[5], a1[0],a1[1],a1[2],a1[3], b0[2],b0[3]);
        HMMA(acc[6], a1[0],a1[1],a1[2],a1[3], b1[0],b1[1]);
        HMMA(acc[7], a1[0],a1[1],a1[2],a1[3], b1[2],b1[3]);
        // k16 slot s1
        LDSM4(a0, stA + aOff1);
        LDSM4(a1, stA + aOff1 + 2048);
        LDSM4(b0, stB + bOff1);
        LDSM4(b1, stB + bOff1 + 2048);
        HMMA(acc[0], a0[0],a0[1],a0[2],a0[3], b0[0],b0[1]);
        HMMA(acc[1], a0[0],a0[1],a0[2],a0[3], b0[2],b0[3]);
        HMMA(acc[2], a0[0],a0[1],a0[2],a0[3], b1[0],b1[1]);
        HMMA(acc[3], a0[0],a0[1],a0[2],a0[3], b1[2],b1[3]);
        HMMA(acc[4], a1[0],a1[1],a1[2],a1[3], b0[0],b0[1]);
        HMMA(acc[5], a1[0],a1[1],a1[2],a1[3], b0[2],b0[3]);
        HMMA(acc[6], a1[0],a1[1],a1[2],a1[3], b1[0],b1[1]);
        HMMA(acc[7], a1[0],a1[1],a1[2],a1[3], b1[2],b1[3]);
    }

    // mainloop done: allow next wave's CTAs to launch (their A-prefetch and
    // pipeline fill overlap our epilogue; B loads gated by their wait).
    GRIDDEP_LAUNCH();

    // ---------------- epilogue: 4 partials -> fused LSTM cell -------------
    __syncthreads();                      // all stages consumed; overlay gb
    float* gb = (float*)smem;             // [4 partial][32 m][66] = 33792 B
    {
        float* myb = gb + (grp * 2 + sub) * (32 * 66);
        const int mrow = lane >> 2;
        const int ncol = 2 * (lane & 3);
#pragma unroll
        for (int i = 0; i < 8; i++) {
            const int mt = i >> 2, n8 = i & 3;
            const int m = mt * 16 + mrow;
            const int n = half * 32 + n8 * 8 + ncol;
            *(float2*)&myb[m * 66 + n]       = make_float2(acc[i][0], acc[i][1]);
            *(float2*)&myb[(m + 8) * 66 + n] = make_float2(acc[i][2], acc[i][3]);
        }
    }
    __syncthreads();

    // 256 threads x 2 cells: CTA covers 8 j x 64 b
#pragma unroll
    for (int k = 0; k < 2; k++) {
        const int c  = tid + k * 256;     // 0..511
        const int b  = c >> 3;
        const int jl = c & 7;
        const int j  = mblk * 8 + jl;
        float gsum[4];
#pragma unroll
        for (int g = 0; g < 4; g++) {
            const int m = g * 8 + jl;
            float s = 0.f;
#pragma unroll
            for (int pp = 0; pp < 4; pp++)
                s += gb[(pp * 32 + m) * 66 + b];
            gsum[g] = s;
        }
        float gi = gsum[0] + bs[j];
        float gf = gsum[1] + bs[1024 + j];
        float gg = gsum[2] + bs[2048 + j];
        float go = gsum[3] + bs[3072 + j];
        float cn = sigm(gf) * Cl[b * Hh + j] + sigm(gi) * tanh_(gg);
        Cl[b * Hh + j] = cn;
        float hn = sigm(go) * tanh_(cn);
        o_h[b * Hh + j] = __float2half(hn);
        if (role == 1 && tt == Tt - 1) Hfin[b * Hh + j] = hn;
    }
}

// ---------------- host launcher ----------------
extern "C" void kernel_launch(void* const* d_in, const int* in_sizes, int n_in,
                              void* d_out, int out_size) {
    const float* x_seq = (const float*)d_in[0];
    const float* h0    = (const float*)d_in[1];
    const float* c0    = (const float*)d_in[2];
    const float* Wih   = (const float*)d_in[3];
    const float* Whh   = (const float*)d_in[4];
    const float* bih   = (const float*)d_in[5];
    const float* bhh   = (const float*)d_in[6];

    cudaFuncSetAttribute(lstm_wave,
                         cudaFuncAttributeMaxDynamicSharedMemorySize, SMEM_TOTAL);

    void *p_xh, *p_w, *p_bs, *p_hh, *p_c, *p_hf;
    cudaGetSymbolAddress(&p_xh, g_xh);
    cudaGetSymbolAddress(&p_w,  g_W);
    cudaGetSymbolAddress(&p_bs, g_bsum);
    cudaGetSymbolAddress(&p_hh, g_Hh);
    cudaGetSymbolAddress(&p_c,  g_C);
    cudaGetSymbolAddress(&p_hf, g_Hf);

    split_x_kernel<<<8192, 256>>>(x_seq, Tt * BH);
    init_state_kernel<<<512, 256>>>(h0, c0, bih, bhh);
    prep_w_kernel<<<8192, 256>>>(Wih, Whh);

    cudaLaunchConfig_t cfg = {};
    cfg.gridDim  = dim3(256, 1, 1);
    cfg.blockDim = dim3(256, 1, 1);
    cfg.dynamicSmemBytes = SMEM_TOTAL;
    cfg.stream = 0;
    cudaLaunchAttribute attrs[1];
    attrs[0].id = cudaLaunchAttributeProgrammaticStreamSerialization;
    attrs[0].val.programmaticStreamSerializationAllowed = 1;
    cfg.attrs = attrs;
    cfg.numAttrs = 1;

    for (int w = 0; w <= Tt; w++) {
        cudaLaunchKernelEx(&cfg, lstm_wave,
            (const __half*)p_w, (const float*)p_bs,
            (const __half*)p_xh,
            (__half*)p_hh, (float*)p_c, (float*)p_hf, w);
    }
    cudaMemcpyAsync(d_out, p_hf, (size_t)BH * sizeof(float),
                    cudaMemcpyDeviceToDevice);
}